// round 14
// baseline (speedup 1.0000x reference)
#include <cuda_runtime.h>
#include <cuda_fp16.h>
#include <math.h>
#include <stdint.h>

#define NROWS 8
#define DTOT  (1u<<20)      // 1048576 columns of U
#define PMAX  4096          // max pass-kernel partial blocks

// ---------------- static device scratch (allocation-free rule) ----------------
__device__ __half   g_wh[NROWS*DTOT];        // 16 MB: Q [n][d][l] (exact small int in fp16)
__device__ float    g_nv[NROWS*DTOT];        // 32 MB: sorted iter-2 residuals
__device__ __half   g_pay[NROWS*DTOT];       // 16 MB: 85*f0+17*f1 (exact int in fp16), sorted order
__device__ unsigned g_ord[DTOT];             //  4 MB: packed nid (8 x 3 bits)
__device__ float    g_part[8*PMAX];          // partials laid out [q][blk]
__device__ float    g_pmin[512], g_pmax[512];
__device__ float    g_min, g_max;
__device__ float    g_coefs[2][8];
__device__ float    g_cnts[2][8];
__device__ int      g_sames[2][7];
__device__ unsigned g_cntm = 0;
__device__ unsigned g_cntp1 = 0;
__device__ unsigned g_cntp2 = 0;

// ---------------- helpers ----------------
__device__ __forceinline__ void cev(float &a, float &b){
    float lo = fminf(a,b), hi = fmaxf(a,b);
    a = lo; b = hi;
}
__device__ __forceinline__ void sortv8(float v[8]){
    cev(v[0],v[1]); cev(v[2],v[3]); cev(v[4],v[5]); cev(v[6],v[7]);
    cev(v[0],v[2]); cev(v[1],v[3]); cev(v[4],v[6]); cev(v[5],v[7]);
    cev(v[1],v[2]); cev(v[5],v[6]);
    cev(v[0],v[4]); cev(v[1],v[5]); cev(v[2],v[6]); cev(v[3],v[7]);
    cev(v[2],v[4]); cev(v[3],v[5]);
    cev(v[1],v[2]); cev(v[3],v[4]); cev(v[5],v[6]);
}
__device__ __forceinline__ void ce3(float &va, int &ia, float &pa, float &vb, int &ib, float &pb){
    bool sw = (va > vb) || (va == vb && ia > ib);
    if (sw){ float tv=va; va=vb; vb=tv; int ti=ia; ia=ib; ib=ti; float tp=pa; pa=pb; pb=tp; }
}
__device__ __forceinline__ void sort8p(float v[8], int id[8], float p[8]){
    ce3(v[0],id[0],p[0],v[1],id[1],p[1]); ce3(v[2],id[2],p[2],v[3],id[3],p[3]); ce3(v[4],id[4],p[4],v[5],id[5],p[5]); ce3(v[6],id[6],p[6],v[7],id[7],p[7]);
    ce3(v[0],id[0],p[0],v[2],id[2],p[2]); ce3(v[1],id[1],p[1],v[3],id[3],p[3]); ce3(v[4],id[4],p[4],v[6],id[6],p[6]); ce3(v[5],id[5],p[5],v[7],id[7],p[7]);
    ce3(v[1],id[1],p[1],v[2],id[2],p[2]); ce3(v[5],id[5],p[5],v[6],id[6],p[6]);
    ce3(v[0],id[0],p[0],v[4],id[4],p[4]); ce3(v[1],id[1],p[1],v[5],id[5],p[5]); ce3(v[2],id[2],p[2],v[6],id[6],p[6]); ce3(v[3],id[3],p[3],v[7],id[7],p[7]);
    ce3(v[2],id[2],p[2],v[4],id[4],p[4]); ce3(v[3],id[3],p[3],v[5],id[5],p[5]);
    ce3(v[1],id[1],p[1],v[2],id[2],p[2]); ce3(v[3],id[3],p[3],v[4],id[4],p[4]); ce3(v[5],id[5],p[5],v[6],id[6],p[6]);
}
__device__ __forceinline__ void ce4(float &va, int &ia, float &pa, float &qa,
                                    float &vb, int &ib, float &pb, float &qb){
    bool sw = (va > vb) || (va == vb && ia > ib);
    if (sw){ float tv=va; va=vb; vb=tv; int ti=ia; ia=ib; ib=ti;
             float tp=pa; pa=pb; pb=tp; float tq=qa; qa=qb; qb=tq; }
}
__device__ __forceinline__ void sort8p2(float v[8], int id[8], float p[8], float q[8]){
    ce4(v[0],id[0],p[0],q[0],v[1],id[1],p[1],q[1]); ce4(v[2],id[2],p[2],q[2],v[3],id[3],p[3],q[3]);
    ce4(v[4],id[4],p[4],q[4],v[5],id[5],p[5],q[5]); ce4(v[6],id[6],p[6],q[6],v[7],id[7],p[7],q[7]);
    ce4(v[0],id[0],p[0],q[0],v[2],id[2],p[2],q[2]); ce4(v[1],id[1],p[1],q[1],v[3],id[3],p[3],q[3]);
    ce4(v[4],id[4],p[4],q[4],v[6],id[6],p[6],q[6]); ce4(v[5],id[5],p[5],q[5],v[7],id[7],p[7],q[7]);
    ce4(v[1],id[1],p[1],q[1],v[2],id[2],p[2],q[2]); ce4(v[5],id[5],p[5],q[5],v[6],id[6],p[6],q[6]);
    ce4(v[0],id[0],p[0],q[0],v[4],id[4],p[4],q[4]); ce4(v[1],id[1],p[1],q[1],v[5],id[5],p[5],q[5]);
    ce4(v[2],id[2],p[2],q[2],v[6],id[6],p[6],q[6]); ce4(v[3],id[3],p[3],q[3],v[7],id[7],p[7],q[7]);
    ce4(v[2],id[2],p[2],q[2],v[4],id[4],p[4],q[4]); ce4(v[3],id[3],p[3],q[3],v[5],id[5],p[5],q[5]);
    ce4(v[1],id[1],p[1],q[1],v[2],id[2],p[2],q[2]); ce4(v[3],id[3],p[3],q[3],v[4],id[4],p[4],q[4]);
    ce4(v[5],id[5],p[5],q[5],v[6],id[6],p[6],q[6]);
}
__device__ __forceinline__ void group_totals_g(const float v[8], const int* sameg, float gt[8]){
    int same[7];
    #pragma unroll
    for (int i=0;i<7;i++) same[i] = sameg[i];
    float gs[8];
    gs[0] = v[0];
    #pragma unroll
    for (int i=1;i<8;i++) gs[i] = v[i] + (same[i-1] ? gs[i-1] : 0.f);
    gt[7] = gs[7];
    #pragma unroll
    for (int i=6;i>=0;i--) gt[i] = same[i] ? gt[i+1] : gs[i];
}

// per-thread d[8] (7 sums + 1 max) -> block reduce -> g_part[q*PMAX+blk]
__device__ __forceinline__ void delta_reduce(float d[8], int tid, int blk){
    #pragma unroll
    for (int off=16; off; off>>=1){
        #pragma unroll
        for (int q=0;q<7;q++) d[q] += __shfl_xor_sync(0xffffffffu, d[q], off);
        d[7] = fmaxf(d[7], __shfl_xor_sync(0xffffffffu, d[7], off));
    }
    __shared__ float sw[8][8];
    int w = tid>>5;
    if ((tid&31)==0){
        #pragma unroll
        for (int q=0;q<8;q++) sw[w][q]=d[q];
    }
    __syncthreads();
    if (tid < 8){
        int q = tid;
        float a = sw[0][q];
        if (q==7){
            #pragma unroll
            for (int w2=1;w2<8;w2++) a = fmaxf(a, sw[w2][q]);
        } else {
            #pragma unroll
            for (int w2=1;w2<8;w2++) a += sw[w2][q];
        }
        g_part[q*PMAX + blk] = a;
    }
}

// tail-block: tree-reduce g_part and compute grouping scalars (256 thr)
__device__ void scalar_tail(const float* __restrict__ thres, int set, int nblk, int tid){
    int q = tid >> 5;
    int lane = tid & 31;
    float a = 0.f;
    for (int p=lane; p<nblk; p+=32){
        float xv = g_part[q*PMAX + p];
        a = (q==7) ? fmaxf(a,xv) : (a+xv);
    }
    #pragma unroll
    for (int off=16; off; off>>=1){
        float b = __shfl_xor_sync(0xffffffffu, a, off);
        a = (q==7) ? fmaxf(a,b) : (a+b);
    }
    __shared__ float sred[8];
    if (lane==0) sred[q] = a;
    __syncthreads();
    if (tid==0){
        float dmax = sred[7];
        float sigt = 1.0f/(1.0f + expf(-thres[0]));
        float sp[7], bv[7];
        int gid[8]; gid[0]=0;
        for (int i=0;i<7;i++){
            float mean = (sred[i]/dmax) * (1.0f/1048576.0f);
            float z = (mean - sigt)/0.01f;
            sp[i] = 1.0f/(1.0f + expf(-z));
            bv[i] = rintf(sp[i]);
            gid[i+1] = gid[i] + (int)bv[i];
        }
        int counts[8]; float glog[8];
        for (int g=0;g<8;g++){ counts[g]=0; glog[g]=0.f; }
        for (int rr=0;rr<8;rr++) counts[gid[rr]]++;
        for (int i=0;i<7;i++) glog[gid[i]] += logf(bv[i]==1.0f ? sp[i] : 1.0f - sp[i]);
        float gg[8];
        for (int g=0;g<8;g++) gg[g] = expf(glog[g]);
        for (int rr=0;rr<8;rr++){ g_coefs[set][rr] = gg[gid[rr]]; g_cnts[set][rr] = (float)counts[gid[rr]]; }
        for (int i=0;i<7;i++) g_sames[set][i] = (bv[i]==0.0f) ? 1 : 0;
    }
}

// ---------------- k_minmax: U min/max with fused last-block reduce ----------------
__global__ __launch_bounds__(256) void k_minmax(const float* __restrict__ U){
    int blk = blockIdx.x;
    int tid = threadIdx.x;
    unsigned t = (unsigned)blk*256u + tid;
    const float4* U4 = reinterpret_cast<const float4*>(U);
    float lo =  INFINITY;
    float hi = -INFINITY;
    #pragma unroll
    for (int i=0;i<16;i++){
        float4 u = U4[t + (unsigned)i*131072u];
        lo = fminf(lo, fminf(fminf(u.x,u.y), fminf(u.z,u.w)));
        hi = fmaxf(hi, fmaxf(fmaxf(u.x,u.y), fmaxf(u.z,u.w)));
    }
    #pragma unroll
    for (int off=16; off; off>>=1){
        lo = fminf(lo, __shfl_xor_sync(0xffffffffu, lo, off));
        hi = fmaxf(hi, __shfl_xor_sync(0xffffffffu, hi, off));
    }
    __shared__ float slo[8], shi[8];
    if ((tid&31)==0){ slo[tid>>5]=lo; shi[tid>>5]=hi; }
    __syncthreads();
    if (tid==0){
        #pragma unroll
        for (int w=1;w<8;w++){ lo=fminf(lo,slo[w]); hi=fmaxf(hi,shi[w]); }
        g_pmin[blk]=lo; g_pmax[blk]=hi;
    }
    __shared__ unsigned s_last;
    __threadfence();
    if (tid==0) s_last = atomicAdd(&g_cntm, 1u);
    __syncthreads();
    if (s_last == 511u){
        float l2 = fminf(g_pmin[tid], g_pmin[tid+256]);
        float h2 = fmaxf(g_pmax[tid], g_pmax[tid+256]);
        #pragma unroll
        for (int off=16; off; off>>=1){
            l2 = fminf(l2, __shfl_xor_sync(0xffffffffu, l2, off));
            h2 = fmaxf(h2, __shfl_xor_sync(0xffffffffu, h2, off));
        }
        __shared__ float sl2[8], sh2[8];
        if ((tid&31)==0){ sl2[tid>>5]=l2; sh2[tid>>5]=h2; }
        __syncthreads();
        if (tid==0){
            #pragma unroll
            for (int w=1;w<8;w++){ l2=fminf(l2,sl2[w]); h2=fmaxf(h2,sh2[w]); }
            g_min = l2; g_max = h2;
            g_cntm = 0;
        }
    }
}

// ---------------- phase 1: pass1 (4 cols/thread) + fused scalar tail ----------------
__global__ __launch_bounds__(256) void k_phase1(const float* __restrict__ U, const float* __restrict__ thres){
    int tid = threadIdx.x;
    unsigned c4 = (unsigned)blockIdx.x*256u + tid;
    float s0 = (g_max - g_min) / 3.0f;
    float v[4][8];
    #pragma unroll
    for (int r=0;r<8;r++){
        float4 u = reinterpret_cast<const float4*>(U)[((size_t)r<<18) + c4];
        v[0][r] = u.x - s0*floorf(u.x/s0);
        v[1][r] = u.y - s0*floorf(u.y/s0);
        v[2][r] = u.z - s0*floorf(u.z/s0);
        v[3][r] = u.w - s0*floorf(u.w/s0);
    }
    float d[8];
    #pragma unroll
    for (int q=0;q<8;q++) d[q]=0.f;
    #pragma unroll
    for (int cc=0;cc<4;cc++){
        sortv8(v[cc]);
        #pragma unroll
        for (int q=0;q<7;q++){
            float dd = v[cc][q+1]-v[cc][q];
            d[q] += dd;
            d[7] = fmaxf(d[7], dd);
        }
    }
    delta_reduce(d, tid, blockIdx.x);

    __shared__ unsigned s_last;
    __threadfence();
    if (tid==0) s_last = atomicAdd(&g_cntp1, 1u);
    __syncthreads();
    if (s_last == 1023u){
        scalar_tail(thres, 0, 1024, tid);
        if (tid==0) g_cntp1 = 0;
    }
}

// ---------------- phase 2: 1 col/thread, stores nv/pay/ord, fused scalar tail ----------
__global__ __launch_bounds__(256) void k_phase2(const float* __restrict__ U, const float* __restrict__ thres){
    int tid = threadIdx.x;
    unsigned c = (unsigned)blockIdx.x*256u + tid;
    float s0 = (g_max - g_min)/3.0f;
    float s1 = s0/5.0f;

    float v[8], u[8], f0[8]; int id[8];
    #pragma unroll
    for (int r=0;r<8;r++){
        float uu = U[(size_t)r*DTOT + c];
        u[r]  = uu;
        f0[r] = floorf(uu/s0);
        v[r]  = uu - s0*f0[r];
        id[r] = r;
    }
    sort8p2(v, id, u, f0);

    float gt[8];
    group_totals_g(v, g_sames[0], gt);

    float nv[8], pay[8]; int nid[8];
    #pragma unroll
    for (int i=0;i<8;i++){
        float mean = gt[i]/g_cnts[0][i];
        float t    = g_coefs[0][i]*mean;
        float f1f  = floorf(t/s1);
        float add  = s1*f1f;
        float v0   = s0*f0[i];
        float vals1 = v0 + add;
        nv[i]  = u[i] - vals1;
        nid[i] = id[i];
        pay[i] = 85.0f*f0[i] + 17.0f*f1f;   // exact small integer
    }
    sort8p(nv, nid, pay);

    unsigned ord = 0;
    #pragma unroll
    for (int i=0;i<8;i++){
        g_nv[(size_t)i*DTOT + c]  = nv[i];
        g_pay[(size_t)i*DTOT + c] = __float2half_rn(pay[i]);
        ord |= (unsigned)nid[i] << (3*i);
    }
    g_ord[c] = ord;

    float d[8];
    d[7] = 0.f;
    #pragma unroll
    for (int q=0;q<7;q++){
        float dd = nv[q+1]-nv[q];
        d[q] = dd;
        d[7] = fmaxf(d[7], dd);
    }
    delta_reduce(d, tid, blockIdx.x);

    __shared__ unsigned s_last;
    __threadfence();
    if (tid==0) s_last = atomicAdd(&g_cntp2, 1u);
    __syncthreads();
    if (s_last == 4095u){
        scalar_tail(thres, 1, 4096, tid);
        if (tid==0) g_cntp2 = 0;
    }
}

// ---------------- final consumer: smem scatter/gather inversion ----------------
__global__ __launch_bounds__(256) void k_final2(){
    __shared__ float sqa[256*9];
    __shared__ float sqb[256*9];
    int tid = threadIdx.x;
    unsigned c2 = (unsigned)blockIdx.x*256u + tid;   // column-pair index
    float s0 = (g_max - g_min)/3.0f;
    float s1 = s0/5.0f;
    float s2 = s1/17.0f;
    float nva[8], nvb[8], paya[8], payb[8];
    #pragma unroll
    for (int i=0;i<8;i++){
        float2 nv2 = reinterpret_cast<const float2*>(g_nv)[((size_t)i<<19) + c2];
        nva[i]=nv2.x; nvb[i]=nv2.y;
        __half2 p2 = reinterpret_cast<const __half2*>(g_pay)[((size_t)i<<19) + c2];
        paya[i]=__low2float(p2); payb[i]=__high2float(p2);
    }
    uint2 ords = reinterpret_cast<const uint2*>(g_ord)[c2];

    float gta[8], gtb[8];
    group_totals_g(nva, g_sames[1], gta);
    group_totals_g(nvb, g_sames[1], gtb);
    #pragma unroll
    for (int j=0;j<8;j++){
        float ta = g_coefs[1][j]*(gta[j]/g_cnts[1][j]);
        float tb = g_coefs[1][j]*(gtb[j]/g_cnts[1][j]);
        float Qa = paya[j] + floorf(ta/s2);
        float Qb = payb[j] + floorf(tb/s2);
        sqa[tid*9 + ((ords.x>>(3*j))&7u)] = Qa;   // scatter to orig-row slot
        sqb[tid*9 + ((ords.y>>(3*j))&7u)] = Qb;
    }
    #pragma unroll
    for (int r=0;r<8;r++){
        __half2 h = __floats2half2_rn(sqa[tid*9 + r], sqb[tid*9 + r]);
        reinterpret_cast<__half2*>(g_wh)[((size_t)r<<19) + c2] = h;
    }
}

// ---------------- fp16 mma.sync GEMM: inline x fp32->fp16 A-staging, cp.async B ----------
#define SA_STRIDE 40
#define SB_STRIDE 136
#define SA_STAGE  (128*SA_STRIDE)
#define SB_STAGE  (32*SB_STRIDE)
#define NSTG 3
#define SMEM_HALFS (NSTG*SA_STAGE + NSTG*SB_STAGE)
#define SMEM_BYTES (SMEM_HALFS*2)

__device__ __forceinline__ void ldsm_x4(uint32_t r[4], uint32_t addr){
    asm volatile("ldmatrix.sync.aligned.m8n8.x4.shared.b16 {%0,%1,%2,%3}, [%4];"
        : "=r"(r[0]),"=r"(r[1]),"=r"(r[2]),"=r"(r[3]) : "r"(addr));
}
__device__ __forceinline__ void ldsm_x4t(uint32_t r[4], uint32_t addr){
    asm volatile("ldmatrix.sync.aligned.m8n8.x4.trans.shared.b16 {%0,%1,%2,%3}, [%4];"
        : "=r"(r[0]),"=r"(r[1]),"=r"(r[2]),"=r"(r[3]) : "r"(addr));
}
__device__ __forceinline__ void mma16816(float c[4], const uint32_t a[4], const uint32_t b0, const uint32_t b1){
    asm volatile("mma.sync.aligned.m16n8k16.row.col.f32.f16.f16.f32 "
        "{%0,%1,%2,%3}, {%4,%5,%6,%7}, {%8,%9}, {%0,%1,%2,%3};"
        : "+f"(c[0]),"+f"(c[1]),"+f"(c[2]),"+f"(c[3])
        : "r"(a[0]),"r"(a[1]),"r"(a[2]),"r"(a[3]), "r"(b0),"r"(b1));
}
__device__ __forceinline__ void cpasync16(uint32_t dst, const void* src){
    asm volatile("cp.async.cg.shared.global [%0], [%1], 16;" :: "r"(dst), "l"(src));
}

// stage loader: B via cp.async (committed as one group); A via LDG fp32 + cvt + STS
__device__ __forceinline__ void gemm_load_stage(
    const float* Axf, const __half* Bn, __half* sA,
    uint32_t sB_u, int bm, int bn, int k0, int st, int tid)
{
    #pragma unroll
    for (int i=0;i<2;i++){
        int ch = tid + i*256;
        int kr = ch >> 4, ns = ch & 15;
        const __half* srcb = Bn + (size_t)(k0+kr)*1024 + bn + ns*8;
        uint32_t offb = (uint32_t)(st*SB_STAGE + kr*SB_STRIDE + ns*8)*2u;
        cpasync16(sB_u + offb, srcb);
    }
    asm volatile("cp.async.commit_group;");
    #pragma unroll
    for (int i=0;i<4;i++){
        int q = tid + i*256;
        int r = q >> 3, j = q & 7;          // 128 rows x 8 segs of 4 floats
        float4 xv = *reinterpret_cast<const float4*>(Axf + (size_t)(bm+r)*8192 + k0 + j*4);
        __half2 h0 = __floats2half2_rn(xv.x, xv.y);
        __half2 h1 = __floats2half2_rn(xv.z, xv.w);
        __half* dst = sA + st*SA_STAGE + r*SA_STRIDE + j*4;
        *reinterpret_cast<__half2*>(dst)     = h0;
        *reinterpret_cast<__half2*>(dst + 2) = h1;
    }
}

__global__ __launch_bounds__(256, 2) void k_gemm_h(const float* __restrict__ x, float* __restrict__ out){
    extern __shared__ __half smem[];
    __half* sA = smem;
    __half* sB = smem + NSTG*SA_STAGE;

    int n  = blockIdx.z;
    int bm = blockIdx.y * 128;
    int bn = blockIdx.x * 128;
    const float*  Axf = x + n*1024;                 // A row b at Axf + b*8192 + d
    const __half* Bn  = g_wh + ((size_t)n << 20);

    int tid  = threadIdx.x;
    int lane = tid & 31;
    int warp = tid >> 5;
    int wm = (warp >> 1) * 32;
    int wn = (warp & 1) * 64;

    uint32_t sA_u = (uint32_t)__cvta_generic_to_shared(sA);
    uint32_t sB_u = (uint32_t)__cvta_generic_to_shared(sB);

    float c[2][8][4];
    #pragma unroll
    for (int mt=0;mt<2;mt++)
        #pragma unroll
        for (int nt=0;nt<8;nt++)
            #pragma unroll
            for (int q=0;q<4;q++) c[mt][nt][q] = 0.f;

    gemm_load_stage(Axf, Bn, sA, sB_u, bm, bn, 0,  0, tid);
    gemm_load_stage(Axf, Bn, sA, sB_u, bm, bn, 32, 1, tid);

    for (int it=0; it<32; it++){
        int st = it % 3;
        if (it < 31) asm volatile("cp.async.wait_group 1;");
        else         asm volatile("cp.async.wait_group 0;");
        __syncthreads();
        if (it + 2 < 32)
            gemm_load_stage(Axf, Bn, sA, sB_u, bm, bn, (it+2)*32, (it+2)%3, tid);

        #pragma unroll
        for (int kk=0; kk<32; kk+=16){
            uint32_t ah[2][4], bf[4][4];
            #pragma unroll
            for (int mt=0; mt<2; mt++){
                int row = wm + mt*16 + (lane & 15);
                int col = kk + ((lane >> 4) << 3);
                uint32_t off = (uint32_t)(st*SA_STAGE + row*SA_STRIDE + col)*2u;
                ldsm_x4(ah[mt], sA_u + off);
            }
            #pragma unroll
            for (int nt2=0; nt2<4; nt2++){
                int krow = kk + (lane & 15);
                int coln = wn + (nt2*2 + (lane >> 4))*8;
                uint32_t off = (uint32_t)(st*SB_STAGE + krow*SB_STRIDE + coln)*2u;
                ldsm_x4t(bf[nt2], sB_u + off);
            }
            #pragma unroll
            for (int mt=0;mt<2;mt++)
                #pragma unroll
                for (int nt2=0;nt2<4;nt2++){
                    mma16816(c[mt][nt2*2+0], ah[mt], bf[nt2][0], bf[nt2][1]);
                    mma16816(c[mt][nt2*2+1], ah[mt], bf[nt2][2], bf[nt2][3]);
                }
        }
    }

    float s2 = ((g_max - g_min)/3.0f/5.0f)/17.0f;
    #pragma unroll
    for (int mt=0;mt<2;mt++){
        int r0 = bm + wm + mt*16 + (lane >> 2);
        #pragma unroll
        for (int nt=0;nt<8;nt++){
            int cb = bn + wn + nt*8 + (lane & 3)*2;
            float2 v0 = make_float2(c[mt][nt][0]*s2, c[mt][nt][1]*s2);
            float2 v1 = make_float2(c[mt][nt][2]*s2, c[mt][nt][3]*s2);
            *reinterpret_cast<float2*>(out + (size_t)r0*8192 + n*1024 + cb)       = v0;
            *reinterpret_cast<float2*>(out + (size_t)(r0+8)*8192 + n*1024 + cb)   = v1;
        }
    }
}

// ---------------- launch ----------------
extern "C" void kernel_launch(void* const* d_in, const int* in_sizes, int n_in,
                              void* d_out, int out_size) {
    const float* x     = (const float*)d_in[0];   // [1024, 8, 1024]
    const float* U     = (const float*)d_in[1];   // [8, 1048576]
    const float* thres = (const float*)d_in[2];   // [1]
    float* out = (float*)d_out;                   // [1024, 8, 1024]

    cudaFuncSetAttribute(k_gemm_h, cudaFuncAttributeMaxDynamicSharedMemorySize, SMEM_BYTES);

    k_minmax<<<512,256>>>(U);                   // U min/max, fused tail reduce
    k_phase1<<<1024,256>>>(U, thres);           // pass1 + fused scalar tail (set 0)
    k_phase2<<<4096,256>>>(U, thres);           // pass2 + stores + fused scalar tail (set 1)
    k_final2<<<2048,256>>>();                   // light consumer: smem-inverted Q, coalesced
    k_gemm_h<<<dim3(8, 8, 8), 256, SMEM_BYTES>>>(x, out);
}

// round 15
// speedup vs baseline: 1.0107x; 1.0107x over previous
#include <cuda_runtime.h>
#include <cuda_fp16.h>
#include <math.h>
#include <stdint.h>

#define NROWS 8
#define DTOT  (1u<<20)      // 1048576 columns of U
#define PMAX  4096          // max pass-kernel partial blocks

// ---------------- static device scratch (allocation-free rule) ----------------
__device__ __half   g_wh[NROWS*DTOT];        // 16 MB: Q [n][d][l] (exact small int in fp16)
__device__ __half   g_xh[NROWS*DTOT];        // 16 MB: x hi half, [n][b][d]
__device__ float    g_nv[NROWS*DTOT];        // 32 MB: sorted iter-2 residuals
__device__ __half   g_pay[NROWS*DTOT];       // 16 MB: 85*f0+17*f1 (exact int in fp16), sorted order
__device__ unsigned g_ord[DTOT];             //  4 MB: packed nid (8 x 3 bits)
__device__ float    g_part[8*PMAX];          // partials laid out [q][blk]
__device__ float    g_pmin[512], g_pmax[512];
__device__ float    g_min, g_max;
__device__ float    g_coefs[2][8];
__device__ float    g_cnts[2][8];
__device__ int      g_sames[2][7];
__device__ unsigned g_cntm = 0;
__device__ unsigned g_cntp1 = 0;
__device__ unsigned g_cntp2 = 0;

// ---------------- helpers ----------------
__device__ __forceinline__ void cev(float &a, float &b){
    float lo = fminf(a,b), hi = fmaxf(a,b);
    a = lo; b = hi;
}
__device__ __forceinline__ void sortv8(float v[8]){
    cev(v[0],v[1]); cev(v[2],v[3]); cev(v[4],v[5]); cev(v[6],v[7]);
    cev(v[0],v[2]); cev(v[1],v[3]); cev(v[4],v[6]); cev(v[5],v[7]);
    cev(v[1],v[2]); cev(v[5],v[6]);
    cev(v[0],v[4]); cev(v[1],v[5]); cev(v[2],v[6]); cev(v[3],v[7]);
    cev(v[2],v[4]); cev(v[3],v[5]);
    cev(v[1],v[2]); cev(v[3],v[4]); cev(v[5],v[6]);
}
__device__ __forceinline__ void ce3(float &va, int &ia, float &pa, float &vb, int &ib, float &pb){
    bool sw = (va > vb) || (va == vb && ia > ib);
    if (sw){ float tv=va; va=vb; vb=tv; int ti=ia; ia=ib; ib=ti; float tp=pa; pa=pb; pb=tp; }
}
__device__ __forceinline__ void sort8p(float v[8], int id[8], float p[8]){
    ce3(v[0],id[0],p[0],v[1],id[1],p[1]); ce3(v[2],id[2],p[2],v[3],id[3],p[3]); ce3(v[4],id[4],p[4],v[5],id[5],p[5]); ce3(v[6],id[6],p[6],v[7],id[7],p[7]);
    ce3(v[0],id[0],p[0],v[2],id[2],p[2]); ce3(v[1],id[1],p[1],v[3],id[3],p[3]); ce3(v[4],id[4],p[4],v[6],id[6],p[6]); ce3(v[5],id[5],p[5],v[7],id[7],p[7]);
    ce3(v[1],id[1],p[1],v[2],id[2],p[2]); ce3(v[5],id[5],p[5],v[6],id[6],p[6]);
    ce3(v[0],id[0],p[0],v[4],id[4],p[4]); ce3(v[1],id[1],p[1],v[5],id[5],p[5]); ce3(v[2],id[2],p[2],v[6],id[6],p[6]); ce3(v[3],id[3],p[3],v[7],id[7],p[7]);
    ce3(v[2],id[2],p[2],v[4],id[4],p[4]); ce3(v[3],id[3],p[3],v[5],id[5],p[5]);
    ce3(v[1],id[1],p[1],v[2],id[2],p[2]); ce3(v[3],id[3],p[3],v[4],id[4],p[4]); ce3(v[5],id[5],p[5],v[6],id[6],p[6]);
}
__device__ __forceinline__ void ce4(float &va, int &ia, float &pa, float &qa,
                                    float &vb, int &ib, float &pb, float &qb){
    bool sw = (va > vb) || (va == vb && ia > ib);
    if (sw){ float tv=va; va=vb; vb=tv; int ti=ia; ia=ib; ib=ti;
             float tp=pa; pa=pb; pb=tp; float tq=qa; qa=qb; qb=tq; }
}
__device__ __forceinline__ void sort8p2(float v[8], int id[8], float p[8], float q[8]){
    ce4(v[0],id[0],p[0],q[0],v[1],id[1],p[1],q[1]); ce4(v[2],id[2],p[2],q[2],v[3],id[3],p[3],q[3]);
    ce4(v[4],id[4],p[4],q[4],v[5],id[5],p[5],q[5]); ce4(v[6],id[6],p[6],q[6],v[7],id[7],p[7],q[7]);
    ce4(v[0],id[0],p[0],q[0],v[2],id[2],p[2],q[2]); ce4(v[1],id[1],p[1],q[1],v[3],id[3],p[3],q[3]);
    ce4(v[4],id[4],p[4],q[4],v[6],id[6],p[6],q[6]); ce4(v[5],id[5],p[5],q[5],v[7],id[7],p[7],q[7]);
    ce4(v[1],id[1],p[1],q[1],v[2],id[2],p[2],q[2]); ce4(v[5],id[5],p[5],q[5],v[6],id[6],p[6],q[6]);
    ce4(v[0],id[0],p[0],q[0],v[4],id[4],p[4],q[4]); ce4(v[1],id[1],p[1],q[1],v[5],id[5],p[5],q[5]);
    ce4(v[2],id[2],p[2],q[2],v[6],id[6],p[6],q[6]); ce4(v[3],id[3],p[3],q[3],v[7],id[7],p[7],q[7]);
    ce4(v[2],id[2],p[2],q[2],v[4],id[4],p[4],q[4]); ce4(v[3],id[3],p[3],q[3],v[5],id[5],p[5],q[5]);
    ce4(v[1],id[1],p[1],q[1],v[2],id[2],p[2],q[2]); ce4(v[3],id[3],p[3],q[3],v[4],id[4],p[4],q[4]);
    ce4(v[5],id[5],p[5],q[5],v[6],id[6],p[6],q[6]);
}
__device__ __forceinline__ void group_totals_g(const float v[8], const int* sameg, float gt[8]){
    int same[7];
    #pragma unroll
    for (int i=0;i<7;i++) same[i] = sameg[i];
    float gs[8];
    gs[0] = v[0];
    #pragma unroll
    for (int i=1;i<8;i++) gs[i] = v[i] + (same[i-1] ? gs[i-1] : 0.f);
    gt[7] = gs[7];
    #pragma unroll
    for (int i=6;i>=0;i--) gt[i] = same[i] ? gt[i+1] : gs[i];
}

// per-thread d[8] (7 sums + 1 max) -> block reduce -> g_part[q*PMAX+blk]
__device__ __forceinline__ void delta_reduce(float d[8], int tid, int blk){
    #pragma unroll
    for (int off=16; off; off>>=1){
        #pragma unroll
        for (int q=0;q<7;q++) d[q] += __shfl_xor_sync(0xffffffffu, d[q], off);
        d[7] = fmaxf(d[7], __shfl_xor_sync(0xffffffffu, d[7], off));
    }
    __shared__ float sw[8][8];
    int w = tid>>5;
    if ((tid&31)==0){
        #pragma unroll
        for (int q=0;q<8;q++) sw[w][q]=d[q];
    }
    __syncthreads();
    if (tid < 8){
        int q = tid;
        float a = sw[0][q];
        if (q==7){
            #pragma unroll
            for (int w2=1;w2<8;w2++) a = fmaxf(a, sw[w2][q]);
        } else {
            #pragma unroll
            for (int w2=1;w2<8;w2++) a += sw[w2][q];
        }
        g_part[q*PMAX + blk] = a;
    }
}

// tail-block: tree-reduce g_part and compute grouping scalars (256 thr)
__device__ void scalar_tail(const float* __restrict__ thres, int set, int nblk, int tid){
    int q = tid >> 5;
    int lane = tid & 31;
    float a = 0.f;
    for (int p=lane; p<nblk; p+=32){
        float xv = g_part[q*PMAX + p];
        a = (q==7) ? fmaxf(a,xv) : (a+xv);
    }
    #pragma unroll
    for (int off=16; off; off>>=1){
        float b = __shfl_xor_sync(0xffffffffu, a, off);
        a = (q==7) ? fmaxf(a,b) : (a+b);
    }
    __shared__ float sred[8];
    if (lane==0) sred[q] = a;
    __syncthreads();
    if (tid==0){
        float dmax = sred[7];
        float sigt = 1.0f/(1.0f + expf(-thres[0]));
        float sp[7], bv[7];
        int gid[8]; gid[0]=0;
        for (int i=0;i<7;i++){
            float mean = (sred[i]/dmax) * (1.0f/1048576.0f);
            float z = (mean - sigt)/0.01f;
            sp[i] = 1.0f/(1.0f + expf(-z));
            bv[i] = rintf(sp[i]);
            gid[i+1] = gid[i] + (int)bv[i];
        }
        int counts[8]; float glog[8];
        for (int g=0;g<8;g++){ counts[g]=0; glog[g]=0.f; }
        for (int rr=0;rr<8;rr++) counts[gid[rr]]++;
        for (int i=0;i<7;i++) glog[gid[i]] += logf(bv[i]==1.0f ? sp[i] : 1.0f - sp[i]);
        float gg[8];
        for (int g=0;g<8;g++) gg[g] = expf(glog[g]);
        for (int rr=0;rr<8;rr++){ g_coefs[set][rr] = gg[gid[rr]]; g_cnts[set][rr] = (float)counts[gid[rr]]; }
        for (int i=0;i<7;i++) g_sames[set][i] = (bv[i]==0.0f) ? 1 : 0;
    }
}

// ---------------- k_minmax: 512 blocks, fused last-block reduce ----------------
__global__ __launch_bounds__(256) void k_minmax(const float* __restrict__ U){
    int blk = blockIdx.x;
    int tid = threadIdx.x;
    unsigned t = (unsigned)blk*256u + tid;
    const float4* U4 = reinterpret_cast<const float4*>(U);
    float lo =  INFINITY;
    float hi = -INFINITY;
    #pragma unroll
    for (int i=0;i<16;i++){
        float4 u = U4[t + (unsigned)i*131072u];
        lo = fminf(lo, fminf(fminf(u.x,u.y), fminf(u.z,u.w)));
        hi = fmaxf(hi, fmaxf(fmaxf(u.x,u.y), fmaxf(u.z,u.w)));
    }
    #pragma unroll
    for (int off=16; off; off>>=1){
        lo = fminf(lo, __shfl_xor_sync(0xffffffffu, lo, off));
        hi = fmaxf(hi, __shfl_xor_sync(0xffffffffu, hi, off));
    }
    __shared__ float slo[8], shi[8];
    if ((tid&31)==0){ slo[tid>>5]=lo; shi[tid>>5]=hi; }
    __syncthreads();
    if (tid==0){
        #pragma unroll
        for (int w=1;w<8;w++){ lo=fminf(lo,slo[w]); hi=fmaxf(hi,shi[w]); }
        g_pmin[blk]=lo; g_pmax[blk]=hi;
    }
    __shared__ unsigned s_last;
    __threadfence();
    if (tid==0) s_last = atomicAdd(&g_cntm, 1u);
    __syncthreads();
    if (s_last == 511u){
        float l2 = fminf(g_pmin[tid], g_pmin[tid+256]);
        float h2 = fmaxf(g_pmax[tid], g_pmax[tid+256]);
        #pragma unroll
        for (int off=16; off; off>>=1){
            l2 = fminf(l2, __shfl_xor_sync(0xffffffffu, l2, off));
            h2 = fmaxf(h2, __shfl_xor_sync(0xffffffffu, h2, off));
        }
        __shared__ float sl2[8], sh2[8];
        if ((tid&31)==0){ sl2[tid>>5]=l2; sh2[tid>>5]=h2; }
        __syncthreads();
        if (tid==0){
            #pragma unroll
            for (int w=1;w<8;w++){ l2=fminf(l2,sl2[w]); h2=fmaxf(h2,sh2[w]); }
            g_min = l2; g_max = h2;
            g_cntm = 0;
        }
    }
}

// ---------------- phase 1 + concurrent split: 3072 blocks ----------------
// blocks 0..2047: split x -> g_xh (independent of g_min)
// blocks 2048..3071: pass1 (4 cols/thread) + fused scalar tail (counter counts ONLY pass1 blocks)
__global__ __launch_bounds__(256) void k_phase1(const float* __restrict__ x,
                                                const float* __restrict__ U,
                                                const float* __restrict__ thres){
    int tid = threadIdx.x;
    int blk = blockIdx.x;
    if (blk < 2048){
        unsigned idx = (unsigned)blk*256u + tid;
        unsigned base = idx*16u;
        unsigned d = base & 1023u;
        unsigned n = (base >> 10) & 7u;
        unsigned b = base >> 13;
        unsigned j = (n << 20) | (b << 10) | d;
        #pragma unroll
        for (int i=0;i<4;i++){
            float4 xv = *reinterpret_cast<const float4*>(x + base + 4u*i);
            __half2 h0 = __floats2half2_rn(xv.x, xv.y);
            __half2 h1 = __floats2half2_rn(xv.z, xv.w);
            *reinterpret_cast<__half2*>(g_xh + j + 4u*i)     = h0;
            *reinterpret_cast<__half2*>(g_xh + j + 4u*i + 2) = h1;
        }
        return;
    }
    int pblk = blk - 2048;
    unsigned c4 = (unsigned)pblk*256u + tid;
    float s0 = (g_max - g_min) / 3.0f;
    float v[4][8];
    #pragma unroll
    for (int r=0;r<8;r++){
        float4 u = reinterpret_cast<const float4*>(U)[((size_t)r<<18) + c4];
        v[0][r] = u.x - s0*floorf(u.x/s0);
        v[1][r] = u.y - s0*floorf(u.y/s0);
        v[2][r] = u.z - s0*floorf(u.z/s0);
        v[3][r] = u.w - s0*floorf(u.w/s0);
    }
    float d[8];
    #pragma unroll
    for (int q=0;q<8;q++) d[q]=0.f;
    #pragma unroll
    for (int cc=0;cc<4;cc++){
        sortv8(v[cc]);
        #pragma unroll
        for (int q=0;q<7;q++){
            float dd = v[cc][q+1]-v[cc][q];
            d[q] += dd;
            d[7] = fmaxf(d[7], dd);
        }
    }
    delta_reduce(d, tid, pblk);

    __shared__ unsigned s_last;
    __threadfence();
    if (tid==0) s_last = atomicAdd(&g_cntp1, 1u);
    __syncthreads();
    if (s_last == 1023u){
        scalar_tail(thres, 0, 1024, tid);
        if (tid==0) g_cntp1 = 0;
    }
}

// ---------------- phase 2: 1 col/thread, stores nv/pay/ord, fused scalar tail ----------
__global__ __launch_bounds__(256) void k_phase2(const float* __restrict__ U, const float* __restrict__ thres){
    int tid = threadIdx.x;
    unsigned c = (unsigned)blockIdx.x*256u + tid;
    float s0 = (g_max - g_min)/3.0f;
    float s1 = s0/5.0f;

    float v[8], u[8], f0[8]; int id[8];
    #pragma unroll
    for (int r=0;r<8;r++){
        float uu = U[(size_t)r*DTOT + c];
        u[r]  = uu;
        f0[r] = floorf(uu/s0);
        v[r]  = uu - s0*f0[r];
        id[r] = r;
    }
    sort8p2(v, id, u, f0);

    float gt[8];
    group_totals_g(v, g_sames[0], gt);

    float nv[8], pay[8]; int nid[8];
    #pragma unroll
    for (int i=0;i<8;i++){
        float mean = gt[i]/g_cnts[0][i];
        float t    = g_coefs[0][i]*mean;
        float f1f  = floorf(t/s1);
        float add  = s1*f1f;
        float v0   = s0*f0[i];
        float vals1 = v0 + add;
        nv[i]  = u[i] - vals1;
        nid[i] = id[i];
        pay[i] = 85.0f*f0[i] + 17.0f*f1f;   // exact small integer
    }
    sort8p(nv, nid, pay);

    unsigned ord = 0;
    #pragma unroll
    for (int i=0;i<8;i++){
        g_nv[(size_t)i*DTOT + c]  = nv[i];
        g_pay[(size_t)i*DTOT + c] = __float2half_rn(pay[i]);
        ord |= (unsigned)nid[i] << (3*i);
    }
    g_ord[c] = ord;

    float d[8];
    d[7] = 0.f;
    #pragma unroll
    for (int q=0;q<7;q++){
        float dd = nv[q+1]-nv[q];
        d[q] = dd;
        d[7] = fmaxf(d[7], dd);
    }
    delta_reduce(d, tid, blockIdx.x);

    __shared__ unsigned s_last;
    __threadfence();
    if (tid==0) s_last = atomicAdd(&g_cntp2, 1u);
    __syncthreads();
    if (s_last == 4095u){
        scalar_tail(thres, 1, 4096, tid);
        if (tid==0) g_cntp2 = 0;
    }
}

// ---------------- final consumer: smem scatter/gather inversion ----------------
__global__ __launch_bounds__(256) void k_final2(){
    __shared__ float sqa[256*9];
    __shared__ float sqb[256*9];
    int tid = threadIdx.x;
    unsigned c2 = (unsigned)blockIdx.x*256u + tid;   // column-pair index
    float s0 = (g_max - g_min)/3.0f;
    float s1 = s0/5.0f;
    float s2 = s1/17.0f;
    float nva[8], nvb[8], paya[8], payb[8];
    #pragma unroll
    for (int i=0;i<8;i++){
        float2 nv2 = reinterpret_cast<const float2*>(g_nv)[((size_t)i<<19) + c2];
        nva[i]=nv2.x; nvb[i]=nv2.y;
        __half2 p2 = reinterpret_cast<const __half2*>(g_pay)[((size_t)i<<19) + c2];
        paya[i]=__low2float(p2); payb[i]=__high2float(p2);
    }
    uint2 ords = reinterpret_cast<const uint2*>(g_ord)[c2];

    float gta[8], gtb[8];
    group_totals_g(nva, g_sames[1], gta);
    group_totals_g(nvb, g_sames[1], gtb);
    #pragma unroll
    for (int j=0;j<8;j++){
        float ta = g_coefs[1][j]*(gta[j]/g_cnts[1][j]);
        float tb = g_coefs[1][j]*(gtb[j]/g_cnts[1][j]);
        float Qa = paya[j] + floorf(ta/s2);
        float Qb = payb[j] + floorf(tb/s2);
        sqa[tid*9 + ((ords.x>>(3*j))&7u)] = Qa;   // scatter to orig-row slot
        sqb[tid*9 + ((ords.y>>(3*j))&7u)] = Qb;
    }
    #pragma unroll
    for (int r=0;r<8;r++){
        __half2 h = __floats2half2_rn(sqa[tid*9 + r], sqb[tid*9 + r]);
        reinterpret_cast<__half2*>(g_wh)[((size_t)r<<19) + c2] = h;
    }
}

// ---------------- fp16 mma.sync GEMM: 3-stage cp.async, 1 sync/iter, x4-trans B ----------
#define SA_STRIDE 40
#define SB_STRIDE 136
#define SA_STAGE  (128*SA_STRIDE)
#define SB_STAGE  (32*SB_STRIDE)
#define NSTG 3
#define SMEM_HALFS (NSTG*SA_STAGE + NSTG*SB_STAGE)
#define SMEM_BYTES (SMEM_HALFS*2)

__device__ __forceinline__ void ldsm_x4(uint32_t r[4], uint32_t addr){
    asm volatile("ldmatrix.sync.aligned.m8n8.x4.shared.b16 {%0,%1,%2,%3}, [%4];"
        : "=r"(r[0]),"=r"(r[1]),"=r"(r[2]),"=r"(r[3]) : "r"(addr));
}
__device__ __forceinline__ void ldsm_x4t(uint32_t r[4], uint32_t addr){
    asm volatile("ldmatrix.sync.aligned.m8n8.x4.trans.shared.b16 {%0,%1,%2,%3}, [%4];"
        : "=r"(r[0]),"=r"(r[1]),"=r"(r[2]),"=r"(r[3]) : "r"(addr));
}
__device__ __forceinline__ void mma16816(float c[4], const uint32_t a[4], const uint32_t b0, const uint32_t b1){
    asm volatile("mma.sync.aligned.m16n8k16.row.col.f32.f16.f16.f32 "
        "{%0,%1,%2,%3}, {%4,%5,%6,%7}, {%8,%9}, {%0,%1,%2,%3};"
        : "+f"(c[0]),"+f"(c[1]),"+f"(c[2]),"+f"(c[3])
        : "r"(a[0]),"r"(a[1]),"r"(a[2]),"r"(a[3]), "r"(b0),"r"(b1));
}
__device__ __forceinline__ void cpasync16(uint32_t dst, const void* src){
    asm volatile("cp.async.cg.shared.global [%0], [%1], 16;" :: "r"(dst), "l"(src));
}

__device__ __forceinline__ void gemm_load_stage(
    const __half* Ah, const __half* Bn,
    uint32_t sA_u, uint32_t sB_u,
    int bm, int bn, int k0, int st, int tid)
{
    #pragma unroll
    for (int i=0;i<2;i++){
        int ch = tid + i*256;
        int r  = ch >> 2, sg = ch & 3;
        const __half* srch = Ah + (size_t)(bm+r)*1024 + k0 + sg*8;
        uint32_t off = (uint32_t)(st*SA_STAGE + r*SA_STRIDE + sg*8)*2u;
        cpasync16(sA_u + off, srch);
        int kr = ch >> 4, ns = ch & 15;
        const __half* srcb = Bn + (size_t)(k0+kr)*1024 + bn + ns*8;
        uint32_t offb = (uint32_t)(st*SB_STAGE + kr*SB_STRIDE + ns*8)*2u;
        cpasync16(sB_u + offb, srcb);
    }
    asm volatile("cp.async.commit_group;");
}

__global__ __launch_bounds__(256) void k_gemm_h(float* __restrict__ out){
    extern __shared__ __half smem[];
    __half* sA = smem;
    __half* sB = smem + NSTG*SA_STAGE;

    int n  = blockIdx.z;
    int bm = blockIdx.y * 128;
    int bn = blockIdx.x * 128;
    const __half* An = g_xh + ((size_t)n << 20);
    const __half* Bn = g_wh + ((size_t)n << 20);

    int tid  = threadIdx.x;
    int lane = tid & 31;
    int warp = tid >> 5;
    int wm = (warp >> 1) * 32;
    int wn = (warp & 1) * 64;

    uint32_t sA_u = (uint32_t)__cvta_generic_to_shared(sA);
    uint32_t sB_u = (uint32_t)__cvta_generic_to_shared(sB);

    float c[2][8][4];
    #pragma unroll
    for (int mt=0;mt<2;mt++)
        #pragma unroll
        for (int nt=0;nt<8;nt++)
            #pragma unroll
            for (int q=0;q<4;q++) c[mt][nt][q] = 0.f;

    gemm_load_stage(An, Bn, sA_u, sB_u, bm, bn, 0,  0, tid);
    gemm_load_stage(An, Bn, sA_u, sB_u, bm, bn, 32, 1, tid);

    for (int it=0; it<32; it++){
        int st = it % 3;
        if (it < 31) asm volatile("cp.async.wait_group 1;");
        else         asm volatile("cp.async.wait_group 0;");
        __syncthreads();
        if (it + 2 < 32)
            gemm_load_stage(An, Bn, sA_u, sB_u, bm, bn, (it+2)*32, (it+2)%3, tid);

        #pragma unroll
        for (int kk=0; kk<32; kk+=16){
            uint32_t ah[2][4], bf[4][4];
            #pragma unroll
            for (int mt=0; mt<2; mt++){
                int row = wm + mt*16 + (lane & 15);
                int col = kk + ((lane >> 4) << 3);
                uint32_t off = (uint32_t)(st*SA_STAGE + row*SA_STRIDE + col)*2u;
                ldsm_x4(ah[mt], sA_u + off);
            }
            #pragma unroll
            for (int nt2=0; nt2<4; nt2++){
                int krow = kk + (lane & 15);
                int coln = wn + (nt2*2 + (lane >> 4))*8;
                uint32_t off = (uint32_t)(st*SB_STAGE + krow*SB_STRIDE + coln)*2u;
                ldsm_x4t(bf[nt2], sB_u + off);
            }
            #pragma unroll
            for (int mt=0;mt<2;mt++)
                #pragma unroll
                for (int nt2=0;nt2<4;nt2++){
                    mma16816(c[mt][nt2*2+0], ah[mt], bf[nt2][0], bf[nt2][1]);
                    mma16816(c[mt][nt2*2+1], ah[mt], bf[nt2][2], bf[nt2][3]);
                }
        }
    }

    float s2 = ((g_max - g_min)/3.0f/5.0f)/17.0f;
    #pragma unroll
    for (int mt=0;mt<2;mt++){
        int r0 = bm + wm + mt*16 + (lane >> 2);
        #pragma unroll
        for (int nt=0;nt<8;nt++){
            int cb = bn + wn + nt*8 + (lane & 3)*2;
            float2 v0 = make_float2(c[mt][nt][0]*s2, c[mt][nt][1]*s2);
            float2 v1 = make_float2(c[mt][nt][2]*s2, c[mt][nt][3]*s2);
            *reinterpret_cast<float2*>(out + (size_t)r0*8192 + n*1024 + cb)       = v0;
            *reinterpret_cast<float2*>(out + (size_t)(r0+8)*8192 + n*1024 + cb)   = v1;
        }
    }
}

// ---------------- launch ----------------
extern "C" void kernel_launch(void* const* d_in, const int* in_sizes, int n_in,
                              void* d_out, int out_size) {
    const float* x     = (const float*)d_in[0];   // [1024, 8, 1024]
    const float* U     = (const float*)d_in[1];   // [8, 1048576]
    const float* thres = (const float*)d_in[2];   // [1]
    float* out = (float*)d_out;                   // [1024, 8, 1024]

    cudaFuncSetAttribute(k_gemm_h, cudaFuncAttributeMaxDynamicSharedMemorySize, SMEM_BYTES);

    k_minmax<<<512,256>>>(U);                   // U min/max, fused tail reduce
    k_phase1<<<3072,256>>>(x, U, thres);        // split(x) concurrent with pass1 + scalar tail
    k_phase2<<<4096,256>>>(U, thres);           // pass2 + stores + fused scalar tail (set 1)
    k_final2<<<2048,256>>>();                   // light consumer: smem-inverted Q, coalesced
    k_gemm_h<<<dim3(8, 8, 8), 256, SMEM_BYTES>>>(out);
}

// round 16
// speedup vs baseline: 1.0262x; 1.0153x over previous
#include <cuda_runtime.h>
#include <cuda_fp16.h>
#include <math.h>
#include <stdint.h>

#define NROWS 8
#define DTOT  (1u<<20)      // 1048576 columns of U
#define PMAX  4096          // max pass-kernel partial blocks

// ---------------- static device scratch (allocation-free rule) ----------------
__device__ __half   g_wh[NROWS*DTOT];        // 16 MB: Q [n][d][l] (exact small int in fp16)
__device__ __half   g_xh[NROWS*DTOT];        // 16 MB: x hi half, [n][b][d]
__device__ float    g_nv[NROWS*DTOT];        // 32 MB: sorted iter-2 residuals
__device__ __half   g_pay[NROWS*DTOT];       // 16 MB: 85*f0+17*f1 (exact int in fp16), sorted order
__device__ unsigned g_ord[DTOT];             //  4 MB: packed nid (8 x 3 bits)
__device__ float    g_part[8*PMAX];          // partials laid out [q][blk]
__device__ float    g_pmin[512], g_pmax[512];
__device__ float    g_min, g_max;
__device__ float    g_coefs[2][8];
__device__ float    g_cnts[2][8];
__device__ int      g_sames[2][7];
__device__ unsigned g_cntm = 0;
__device__ unsigned g_cntp1 = 0;
__device__ unsigned g_cntp2 = 0;

// ---------------- helpers ----------------
__device__ __forceinline__ void cev(float &a, float &b){
    float lo = fminf(a,b), hi = fmaxf(a,b);
    a = lo; b = hi;
}
__device__ __forceinline__ void sortv8(float v[8]){
    cev(v[0],v[1]); cev(v[2],v[3]); cev(v[4],v[5]); cev(v[6],v[7]);
    cev(v[0],v[2]); cev(v[1],v[3]); cev(v[4],v[6]); cev(v[5],v[7]);
    cev(v[1],v[2]); cev(v[5],v[6]);
    cev(v[0],v[4]); cev(v[1],v[5]); cev(v[2],v[6]); cev(v[3],v[7]);
    cev(v[2],v[4]); cev(v[3],v[5]);
    cev(v[1],v[2]); cev(v[3],v[4]); cev(v[5],v[6]);
}
__device__ __forceinline__ void ce3(float &va, int &ia, float &pa, float &vb, int &ib, float &pb){
    bool sw = (va > vb) || (va == vb && ia > ib);
    if (sw){ float tv=va; va=vb; vb=tv; int ti=ia; ia=ib; ib=ti; float tp=pa; pa=pb; pb=tp; }
}
__device__ __forceinline__ void sort8p(float v[8], int id[8], float p[8]){
    ce3(v[0],id[0],p[0],v[1],id[1],p[1]); ce3(v[2],id[2],p[2],v[3],id[3],p[3]); ce3(v[4],id[4],p[4],v[5],id[5],p[5]); ce3(v[6],id[6],p[6],v[7],id[7],p[7]);
    ce3(v[0],id[0],p[0],v[2],id[2],p[2]); ce3(v[1],id[1],p[1],v[3],id[3],p[3]); ce3(v[4],id[4],p[4],v[6],id[6],p[6]); ce3(v[5],id[5],p[5],v[7],id[7],p[7]);
    ce3(v[1],id[1],p[1],v[2],id[2],p[2]); ce3(v[5],id[5],p[5],v[6],id[6],p[6]);
    ce3(v[0],id[0],p[0],v[4],id[4],p[4]); ce3(v[1],id[1],p[1],v[5],id[5],p[5]); ce3(v[2],id[2],p[2],v[6],id[6],p[6]); ce3(v[3],id[3],p[3],v[7],id[7],p[7]);
    ce3(v[2],id[2],p[2],v[4],id[4],p[4]); ce3(v[3],id[3],p[3],v[5],id[5],p[5]);
    ce3(v[1],id[1],p[1],v[2],id[2],p[2]); ce3(v[3],id[3],p[3],v[4],id[4],p[4]); ce3(v[5],id[5],p[5],v[6],id[6],p[6]);
}
__device__ __forceinline__ void ce4(float &va, int &ia, float &pa, float &qa,
                                    float &vb, int &ib, float &pb, float &qb){
    bool sw = (va > vb) || (va == vb && ia > ib);
    if (sw){ float tv=va; va=vb; vb=tv; int ti=ia; ia=ib; ib=ti;
             float tp=pa; pa=pb; pb=tp; float tq=qa; qa=qb; qb=tq; }
}
__device__ __forceinline__ void sort8p2(float v[8], int id[8], float p[8], float q[8]){
    ce4(v[0],id[0],p[0],q[0],v[1],id[1],p[1],q[1]); ce4(v[2],id[2],p[2],q[2],v[3],id[3],p[3],q[3]);
    ce4(v[4],id[4],p[4],q[4],v[5],id[5],p[5],q[5]); ce4(v[6],id[6],p[6],q[6],v[7],id[7],p[7],q[7]);
    ce4(v[0],id[0],p[0],q[0],v[2],id[2],p[2],q[2]); ce4(v[1],id[1],p[1],q[1],v[3],id[3],p[3],q[3]);
    ce4(v[4],id[4],p[4],q[4],v[6],id[6],p[6],q[6]); ce4(v[5],id[5],p[5],q[5],v[7],id[7],p[7],q[7]);
    ce4(v[1],id[1],p[1],q[1],v[2],id[2],p[2],q[2]); ce4(v[5],id[5],p[5],q[5],v[6],id[6],p[6],q[6]);
    ce4(v[0],id[0],p[0],q[0],v[4],id[4],p[4],q[4]); ce4(v[1],id[1],p[1],q[1],v[5],id[5],p[5],q[5]);
    ce4(v[2],id[2],p[2],q[2],v[6],id[6],p[6],q[6]); ce4(v[3],id[3],p[3],q[3],v[7],id[7],p[7],q[7]);
    ce4(v[2],id[2],p[2],q[2],v[4],id[4],p[4],q[4]); ce4(v[3],id[3],p[3],q[3],v[5],id[5],p[5],q[5]);
    ce4(v[1],id[1],p[1],q[1],v[2],id[2],p[2],q[2]); ce4(v[3],id[3],p[3],q[3],v[4],id[4],p[4],q[4]);
    ce4(v[5],id[5],p[5],q[5],v[6],id[6],p[6],q[6]);
}
__device__ __forceinline__ void group_totals_g(const float v[8], const int* sameg, float gt[8]){
    int same[7];
    #pragma unroll
    for (int i=0;i<7;i++) same[i] = sameg[i];
    float gs[8];
    gs[0] = v[0];
    #pragma unroll
    for (int i=1;i<8;i++) gs[i] = v[i] + (same[i-1] ? gs[i-1] : 0.f);
    gt[7] = gs[7];
    #pragma unroll
    for (int i=6;i>=0;i--) gt[i] = same[i] ? gt[i+1] : gs[i];
}

// per-thread d[8] (7 sums + 1 max) -> block reduce -> g_part[q*PMAX+blk]
__device__ __forceinline__ void delta_reduce(float d[8], int tid, int blk){
    #pragma unroll
    for (int off=16; off; off>>=1){
        #pragma unroll
        for (int q=0;q<7;q++) d[q] += __shfl_xor_sync(0xffffffffu, d[q], off);
        d[7] = fmaxf(d[7], __shfl_xor_sync(0xffffffffu, d[7], off));
    }
    __shared__ float sw[8][8];
    int w = tid>>5;
    if ((tid&31)==0){
        #pragma unroll
        for (int q=0;q<8;q++) sw[w][q]=d[q];
    }
    __syncthreads();
    if (tid < 8){
        int q = tid;
        float a = sw[0][q];
        if (q==7){
            #pragma unroll
            for (int w2=1;w2<8;w2++) a = fmaxf(a, sw[w2][q]);
        } else {
            #pragma unroll
            for (int w2=1;w2<8;w2++) a += sw[w2][q];
        }
        g_part[q*PMAX + blk] = a;
    }
}

// tail-block: tree-reduce g_part and compute grouping scalars (256 thr)
__device__ void scalar_tail(const float* __restrict__ thres, int set, int nblk, int tid){
    int q = tid >> 5;
    int lane = tid & 31;
    float a = 0.f;
    for (int p=lane; p<nblk; p+=32){
        float xv = g_part[q*PMAX + p];
        a = (q==7) ? fmaxf(a,xv) : (a+xv);
    }
    #pragma unroll
    for (int off=16; off; off>>=1){
        float b = __shfl_xor_sync(0xffffffffu, a, off);
        a = (q==7) ? fmaxf(a,b) : (a+b);
    }
    __shared__ float sred[8];
    if (lane==0) sred[q] = a;
    __syncthreads();
    if (tid==0){
        float dmax = sred[7];
        float sigt = 1.0f/(1.0f + expf(-thres[0]));
        float sp[7], bv[7];
        int gid[8]; gid[0]=0;
        for (int i=0;i<7;i++){
            float mean = (sred[i]/dmax) * (1.0f/1048576.0f);
            float z = (mean - sigt)/0.01f;
            sp[i] = 1.0f/(1.0f + expf(-z));
            bv[i] = rintf(sp[i]);
            gid[i+1] = gid[i] + (int)bv[i];
        }
        int counts[8]; float glog[8];
        for (int g=0;g<8;g++){ counts[g]=0; glog[g]=0.f; }
        for (int rr=0;rr<8;rr++) counts[gid[rr]]++;
        for (int i=0;i<7;i++) glog[gid[i]] += logf(bv[i]==1.0f ? sp[i] : 1.0f - sp[i]);
        float gg[8];
        for (int g=0;g<8;g++) gg[g] = expf(glog[g]);
        for (int rr=0;rr<8;rr++){ g_coefs[set][rr] = gg[gid[rr]]; g_cnts[set][rr] = (float)counts[gid[rr]]; }
        for (int i=0;i<7;i++) g_sames[set][i] = (bv[i]==0.0f) ? 1 : 0;
    }
}

// ---------------- k_minmax: 512 blocks, fused last-block reduce ----------------
__global__ __launch_bounds__(256) void k_minmax(const float* __restrict__ U){
    int blk = blockIdx.x;
    int tid = threadIdx.x;
    unsigned t = (unsigned)blk*256u + tid;
    const float4* U4 = reinterpret_cast<const float4*>(U);
    float lo =  INFINITY;
    float hi = -INFINITY;
    #pragma unroll
    for (int i=0;i<16;i++){
        float4 u = U4[t + (unsigned)i*131072u];
        lo = fminf(lo, fminf(fminf(u.x,u.y), fminf(u.z,u.w)));
        hi = fmaxf(hi, fmaxf(fmaxf(u.x,u.y), fmaxf(u.z,u.w)));
    }
    #pragma unroll
    for (int off=16; off; off>>=1){
        lo = fminf(lo, __shfl_xor_sync(0xffffffffu, lo, off));
        hi = fmaxf(hi, __shfl_xor_sync(0xffffffffu, hi, off));
    }
    __shared__ float slo[8], shi[8];
    if ((tid&31)==0){ slo[tid>>5]=lo; shi[tid>>5]=hi; }
    __syncthreads();
    if (tid==0){
        #pragma unroll
        for (int w=1;w<8;w++){ lo=fminf(lo,slo[w]); hi=fmaxf(hi,shi[w]); }
        g_pmin[blk]=lo; g_pmax[blk]=hi;
    }
    __shared__ unsigned s_last;
    __threadfence();
    if (tid==0) s_last = atomicAdd(&g_cntm, 1u);
    __syncthreads();
    if (s_last == 511u){
        float l2 = fminf(g_pmin[tid], g_pmin[tid+256]);
        float h2 = fmaxf(g_pmax[tid], g_pmax[tid+256]);
        #pragma unroll
        for (int off=16; off; off>>=1){
            l2 = fminf(l2, __shfl_xor_sync(0xffffffffu, l2, off));
            h2 = fmaxf(h2, __shfl_xor_sync(0xffffffffu, h2, off));
        }
        __shared__ float sl2[8], sh2[8];
        if ((tid&31)==0){ sl2[tid>>5]=l2; sh2[tid>>5]=h2; }
        __syncthreads();
        if (tid==0){
            #pragma unroll
            for (int w=1;w<8;w++){ l2=fminf(l2,sl2[w]); h2=fmaxf(h2,sh2[w]); }
            g_min = l2; g_max = h2;
            g_cntm = 0;
        }
    }
}

// ---------------- phase 1 + concurrent split: 3072 blocks ----------------
// blocks 0..1023: pass1 (4 cols/thread) + fused scalar tail -- scheduled FIRST
// blocks 1024..3071: split x -> g_xh (independent of g_min), fills SMs behind pass1
__global__ __launch_bounds__(256) void k_phase1(const float* __restrict__ x,
                                                const float* __restrict__ U,
                                                const float* __restrict__ thres){
    int tid = threadIdx.x;
    int blk = blockIdx.x;
    if (blk >= 1024){
        int sblk = blk - 1024;
        unsigned idx = (unsigned)sblk*256u + tid;
        unsigned base = idx*16u;
        unsigned d = base & 1023u;
        unsigned n = (base >> 10) & 7u;
        unsigned b = base >> 13;
        unsigned j = (n << 20) | (b << 10) | d;
        #pragma unroll
        for (int i=0;i<4;i++){
            float4 xv = *reinterpret_cast<const float4*>(x + base + 4u*i);
            __half2 h0 = __floats2half2_rn(xv.x, xv.y);
            __half2 h1 = __floats2half2_rn(xv.z, xv.w);
            *reinterpret_cast<__half2*>(g_xh + j + 4u*i)     = h0;
            *reinterpret_cast<__half2*>(g_xh + j + 4u*i + 2) = h1;
        }
        return;
    }
    unsigned c4 = (unsigned)blk*256u + tid;
    float s0 = (g_max - g_min) / 3.0f;
    float v[4][8];
    #pragma unroll
    for (int r=0;r<8;r++){
        float4 u = reinterpret_cast<const float4*>(U)[((size_t)r<<18) + c4];
        v[0][r] = u.x - s0*floorf(u.x/s0);
        v[1][r] = u.y - s0*floorf(u.y/s0);
        v[2][r] = u.z - s0*floorf(u.z/s0);
        v[3][r] = u.w - s0*floorf(u.w/s0);
    }
    float d[8];
    #pragma unroll
    for (int q=0;q<8;q++) d[q]=0.f;
    #pragma unroll
    for (int cc=0;cc<4;cc++){
        sortv8(v[cc]);
        #pragma unroll
        for (int q=0;q<7;q++){
            float dd = v[cc][q+1]-v[cc][q];
            d[q] += dd;
            d[7] = fmaxf(d[7], dd);
        }
    }
    delta_reduce(d, tid, blk);

    __shared__ unsigned s_last;
    __threadfence();
    if (tid==0) s_last = atomicAdd(&g_cntp1, 1u);
    __syncthreads();
    if (s_last == 1023u){
        scalar_tail(thres, 0, 1024, tid);
        if (tid==0) g_cntp1 = 0;
    }
}

// ---------------- phase 2: 1 col/thread, stores nv/pay/ord, fused scalar tail ----------
__global__ __launch_bounds__(256) void k_phase2(const float* __restrict__ U, const float* __restrict__ thres){
    int tid = threadIdx.x;
    unsigned c = (unsigned)blockIdx.x*256u + tid;
    float s0 = (g_max - g_min)/3.0f;
    float s1 = s0/5.0f;

    float v[8], u[8], f0[8]; int id[8];
    #pragma unroll
    for (int r=0;r<8;r++){
        float uu = U[(size_t)r*DTOT + c];
        u[r]  = uu;
        f0[r] = floorf(uu/s0);
        v[r]  = uu - s0*f0[r];
        id[r] = r;
    }
    sort8p2(v, id, u, f0);

    float gt[8];
    group_totals_g(v, g_sames[0], gt);

    float nv[8], pay[8]; int nid[8];
    #pragma unroll
    for (int i=0;i<8;i++){
        float mean = gt[i]/g_cnts[0][i];
        float t    = g_coefs[0][i]*mean;
        float f1f  = floorf(t/s1);
        float add  = s1*f1f;
        float v0   = s0*f0[i];
        float vals1 = v0 + add;
        nv[i]  = u[i] - vals1;
        nid[i] = id[i];
        pay[i] = 85.0f*f0[i] + 17.0f*f1f;   // exact small integer
    }
    sort8p(nv, nid, pay);

    unsigned ord = 0;
    #pragma unroll
    for (int i=0;i<8;i++){
        g_nv[(size_t)i*DTOT + c]  = nv[i];
        g_pay[(size_t)i*DTOT + c] = __float2half_rn(pay[i]);
        ord |= (unsigned)nid[i] << (3*i);
    }
    g_ord[c] = ord;

    float d[8];
    d[7] = 0.f;
    #pragma unroll
    for (int q=0;q<7;q++){
        float dd = nv[q+1]-nv[q];
        d[q] = dd;
        d[7] = fmaxf(d[7], dd);
    }
    delta_reduce(d, tid, blockIdx.x);

    __shared__ unsigned s_last;
    __threadfence();
    if (tid==0) s_last = atomicAdd(&g_cntp2, 1u);
    __syncthreads();
    if (s_last == 4095u){
        scalar_tail(thres, 1, 4096, tid);
        if (tid==0) g_cntp2 = 0;
    }
}

// ---------------- final consumer: smem scatter/gather inversion ----------------
__global__ __launch_bounds__(256) void k_final2(){
    __shared__ float sqa[256*9];
    __shared__ float sqb[256*9];
    int tid = threadIdx.x;
    unsigned c2 = (unsigned)blockIdx.x*256u + tid;   // column-pair index
    float s0 = (g_max - g_min)/3.0f;
    float s1 = s0/5.0f;
    float s2 = s1/17.0f;
    float nva[8], nvb[8], paya[8], payb[8];
    #pragma unroll
    for (int i=0;i<8;i++){
        float2 nv2 = reinterpret_cast<const float2*>(g_nv)[((size_t)i<<19) + c2];
        nva[i]=nv2.x; nvb[i]=nv2.y;
        __half2 p2 = reinterpret_cast<const __half2*>(g_pay)[((size_t)i<<19) + c2];
        paya[i]=__low2float(p2); payb[i]=__high2float(p2);
    }
    uint2 ords = reinterpret_cast<const uint2*>(g_ord)[c2];

    float gta[8], gtb[8];
    group_totals_g(nva, g_sames[1], gta);
    group_totals_g(nvb, g_sames[1], gtb);
    #pragma unroll
    for (int j=0;j<8;j++){
        float ta = g_coefs[1][j]*(gta[j]/g_cnts[1][j]);
        float tb = g_coefs[1][j]*(gtb[j]/g_cnts[1][j]);
        float Qa = paya[j] + floorf(ta/s2);
        float Qb = payb[j] + floorf(tb/s2);
        sqa[tid*9 + ((ords.x>>(3*j))&7u)] = Qa;   // scatter to orig-row slot
        sqb[tid*9 + ((ords.y>>(3*j))&7u)] = Qb;
    }
    #pragma unroll
    for (int r=0;r<8;r++){
        __half2 h = __floats2half2_rn(sqa[tid*9 + r], sqb[tid*9 + r]);
        reinterpret_cast<__half2*>(g_wh)[((size_t)r<<19) + c2] = h;
    }
}

// ---------------- fp16 mma.sync GEMM: 3-stage cp.async, 1 sync/iter, x4-trans B ----------
#define SA_STRIDE 40
#define SB_STRIDE 136
#define SA_STAGE  (128*SA_STRIDE)
#define SB_STAGE  (32*SB_STRIDE)
#define NSTG 3
#define SMEM_HALFS (NSTG*SA_STAGE + NSTG*SB_STAGE)
#define SMEM_BYTES (SMEM_HALFS*2)

__device__ __forceinline__ void ldsm_x4(uint32_t r[4], uint32_t addr){
    asm volatile("ldmatrix.sync.aligned.m8n8.x4.shared.b16 {%0,%1,%2,%3}, [%4];"
        : "=r"(r[0]),"=r"(r[1]),"=r"(r[2]),"=r"(r[3]) : "r"(addr));
}
__device__ __forceinline__ void ldsm_x4t(uint32_t r[4], uint32_t addr){
    asm volatile("ldmatrix.sync.aligned.m8n8.x4.trans.shared.b16 {%0,%1,%2,%3}, [%4];"
        : "=r"(r[0]),"=r"(r[1]),"=r"(r[2]),"=r"(r[3]) : "r"(addr));
}
__device__ __forceinline__ void mma16816(float c[4], const uint32_t a[4], const uint32_t b0, const uint32_t b1){
    asm volatile("mma.sync.aligned.m16n8k16.row.col.f32.f16.f16.f32 "
        "{%0,%1,%2,%3}, {%4,%5,%6,%7}, {%8,%9}, {%0,%1,%2,%3};"
        : "+f"(c[0]),"+f"(c[1]),"+f"(c[2]),"+f"(c[3])
        : "r"(a[0]),"r"(a[1]),"r"(a[2]),"r"(a[3]), "r"(b0),"r"(b1));
}
__device__ __forceinline__ void cpasync16(uint32_t dst, const void* src){
    asm volatile("cp.async.cg.shared.global [%0], [%1], 16;" :: "r"(dst), "l"(src));
}

__device__ __forceinline__ void gemm_load_stage(
    const __half* Ah, const __half* Bn,
    uint32_t sA_u, uint32_t sB_u,
    int bm, int bn, int k0, int st, int tid)
{
    #pragma unroll
    for (int i=0;i<2;i++){
        int ch = tid + i*256;
        int r  = ch >> 2, sg = ch & 3;
        const __half* srch = Ah + (size_t)(bm+r)*1024 + k0 + sg*8;
        uint32_t off = (uint32_t)(st*SA_STAGE + r*SA_STRIDE + sg*8)*2u;
        cpasync16(sA_u + off, srch);
        int kr = ch >> 4, ns = ch & 15;
        const __half* srcb = Bn + (size_t)(k0+kr)*1024 + bn + ns*8;
        uint32_t offb = (uint32_t)(st*SB_STAGE + kr*SB_STRIDE + ns*8)*2u;
        cpasync16(sB_u + offb, srcb);
    }
    asm volatile("cp.async.commit_group;");
}

__global__ __launch_bounds__(256) void k_gemm_h(float* __restrict__ out){
    extern __shared__ __half smem[];
    __half* sA = smem;
    __half* sB = smem + NSTG*SA_STAGE;

    int n  = blockIdx.z;
    int bm = blockIdx.y * 128;
    int bn = blockIdx.x * 128;
    const __half* An = g_xh + ((size_t)n << 20);
    const __half* Bn = g_wh + ((size_t)n << 20);

    int tid  = threadIdx.x;
    int lane = tid & 31;
    int warp = tid >> 5;
    int wm = (warp >> 1) * 32;
    int wn = (warp & 1) * 64;

    uint32_t sA_u = (uint32_t)__cvta_generic_to_shared(sA);
    uint32_t sB_u = (uint32_t)__cvta_generic_to_shared(sB);

    float c[2][8][4];
    #pragma unroll
    for (int mt=0;mt<2;mt++)
        #pragma unroll
        for (int nt=0;nt<8;nt++)
            #pragma unroll
            for (int q=0;q<4;q++) c[mt][nt][q] = 0.f;

    gemm_load_stage(An, Bn, sA_u, sB_u, bm, bn, 0,  0, tid);
    gemm_load_stage(An, Bn, sA_u, sB_u, bm, bn, 32, 1, tid);

    for (int it=0; it<32; it++){
        int st = it % 3;
        if (it < 31) asm volatile("cp.async.wait_group 1;");
        else         asm volatile("cp.async.wait_group 0;");
        __syncthreads();
        if (it + 2 < 32)
            gemm_load_stage(An, Bn, sA_u, sB_u, bm, bn, (it+2)*32, (it+2)%3, tid);

        #pragma unroll
        for (int kk=0; kk<32; kk+=16){
            uint32_t ah[2][4], bf[4][4];
            #pragma unroll
            for (int mt=0; mt<2; mt++){
                int row = wm + mt*16 + (lane & 15);
                int col = kk + ((lane >> 4) << 3);
                uint32_t off = (uint32_t)(st*SA_STAGE + row*SA_STRIDE + col)*2u;
                ldsm_x4(ah[mt], sA_u + off);
            }
            #pragma unroll
            for (int nt2=0; nt2<4; nt2++){
                int krow = kk + (lane & 15);
                int coln = wn + (nt2*2 + (lane >> 4))*8;
                uint32_t off = (uint32_t)(st*SB_STAGE + krow*SB_STRIDE + coln)*2u;
                ldsm_x4t(bf[nt2], sB_u + off);
            }
            #pragma unroll
            for (int mt=0;mt<2;mt++)
                #pragma unroll
                for (int nt2=0;nt2<4;nt2++){
                    mma16816(c[mt][nt2*2+0], ah[mt], bf[nt2][0], bf[nt2][1]);
                    mma16816(c[mt][nt2*2+1], ah[mt], bf[nt2][2], bf[nt2][3]);
                }
        }
    }

    float s2 = ((g_max - g_min)/3.0f/5.0f)/17.0f;
    #pragma unroll
    for (int mt=0;mt<2;mt++){
        int r0 = bm + wm + mt*16 + (lane >> 2);
        #pragma unroll
        for (int nt=0;nt<8;nt++){
            int cb = bn + wn + nt*8 + (lane & 3)*2;
            float2 v0 = make_float2(c[mt][nt][0]*s2, c[mt][nt][1]*s2);
            float2 v1 = make_float2(c[mt][nt][2]*s2, c[mt][nt][3]*s2);
            *reinterpret_cast<float2*>(out + (size_t)r0*8192 + n*1024 + cb)       = v0;
            *reinterpret_cast<float2*>(out + (size_t)(r0+8)*8192 + n*1024 + cb)   = v1;
        }
    }
}

// ---------------- launch ----------------
extern "C" void kernel_launch(void* const* d_in, const int* in_sizes, int n_in,
                              void* d_out, int out_size) {
    const float* x     = (const float*)d_in[0];   // [1024, 8, 1024]
    const float* U     = (const float*)d_in[1];   // [8, 1048576]
    const float* thres = (const float*)d_in[2];   // [1]
    float* out = (float*)d_out;                   // [1024, 8, 1024]

    cudaFuncSetAttribute(k_gemm_h, cudaFuncAttributeMaxDynamicSharedMemorySize, SMEM_BYTES);

    k_minmax<<<512,256>>>(U);                   // U min/max, fused tail reduce
    k_phase1<<<3072,256>>>(x, U, thres);        // pass1 FIRST (blocks 0..1023) + split behind
    k_phase2<<<4096,256>>>(U, thres);           // pass2 + stores + fused scalar tail (set 1)
    k_final2<<<2048,256>>>();                   // light consumer: smem-inverted Q, coalesced
    k_gemm_h<<<dim3(8, 8, 8), 256, SMEM_BYTES>>>(out);
}

// round 17
// speedup vs baseline: 1.0508x; 1.0240x over previous
#include <cuda_runtime.h>
#include <cuda_fp16.h>
#include <math.h>
#include <stdint.h>

#define NROWS 8
#define DTOT  (1u<<20)      // 1048576 columns of U
#define PMAX  4096          // max pass-kernel partial blocks

// ---------------- static device scratch (allocation-free rule) ----------------
__device__ __half   g_wh[NROWS*DTOT];        // 16 MB: Q [n][d][l] (exact small int in fp16)
__device__ __half   g_xh[NROWS*DTOT];        // 16 MB: x hi half, [n][b][d]
__device__ float    g_nv[NROWS*DTOT];        // 32 MB: sorted iter-2 residuals
__device__ __half   g_pay[NROWS*DTOT];       // 16 MB: 85*f0+17*f1 (exact int in fp16), sorted order
__device__ unsigned g_ord[DTOT];             //  4 MB: packed nid (8 x 3 bits)
__device__ float    g_part[8*PMAX];          // partials laid out [q][blk]
__device__ float    g_pmin[512], g_pmax[512];
__device__ float    g_min, g_max;
__device__ float    g_coefs[2][8];
__device__ float    g_cnts[2][8];
__device__ int      g_sames[2][7];
__device__ unsigned g_cntm = 0;
__device__ unsigned g_cntp1 = 0;
__device__ unsigned g_cntp2 = 0;

// ---------------- helpers ----------------
__device__ __forceinline__ void cev(float &a, float &b){
    float lo = fminf(a,b), hi = fmaxf(a,b);
    a = lo; b = hi;
}
__device__ __forceinline__ void sortv8(float v[8]){
    cev(v[0],v[1]); cev(v[2],v[3]); cev(v[4],v[5]); cev(v[6],v[7]);
    cev(v[0],v[2]); cev(v[1],v[3]); cev(v[4],v[6]); cev(v[5],v[7]);
    cev(v[1],v[2]); cev(v[5],v[6]);
    cev(v[0],v[4]); cev(v[1],v[5]); cev(v[2],v[6]); cev(v[3],v[7]);
    cev(v[2],v[4]); cev(v[3],v[5]);
    cev(v[1],v[2]); cev(v[3],v[4]); cev(v[5],v[6]);
}
__device__ __forceinline__ void ce3(float &va, int &ia, float &pa, float &vb, int &ib, float &pb){
    bool sw = (va > vb) || (va == vb && ia > ib);
    if (sw){ float tv=va; va=vb; vb=tv; int ti=ia; ia=ib; ib=ti; float tp=pa; pa=pb; pb=tp; }
}
__device__ __forceinline__ void sort8p(float v[8], int id[8], float p[8]){
    ce3(v[0],id[0],p[0],v[1],id[1],p[1]); ce3(v[2],id[2],p[2],v[3],id[3],p[3]); ce3(v[4],id[4],p[4],v[5],id[5],p[5]); ce3(v[6],id[6],p[6],v[7],id[7],p[7]);
    ce3(v[0],id[0],p[0],v[2],id[2],p[2]); ce3(v[1],id[1],p[1],v[3],id[3],p[3]); ce3(v[4],id[4],p[4],v[6],id[6],p[6]); ce3(v[5],id[5],p[5],v[7],id[7],p[7]);
    ce3(v[1],id[1],p[1],v[2],id[2],p[2]); ce3(v[5],id[5],p[5],v[6],id[6],p[6]);
    ce3(v[0],id[0],p[0],v[4],id[4],p[4]); ce3(v[1],id[1],p[1],v[5],id[5],p[5]); ce3(v[2],id[2],p[2],v[6],id[6],p[6]); ce3(v[3],id[3],p[3],v[7],id[7],p[7]);
    ce3(v[2],id[2],p[2],v[4],id[4],p[4]); ce3(v[3],id[3],p[3],v[5],id[5],p[5]);
    ce3(v[1],id[1],p[1],v[2],id[2],p[2]); ce3(v[3],id[3],p[3],v[4],id[4],p[4]); ce3(v[5],id[5],p[5],v[6],id[6],p[6]);
}
__device__ __forceinline__ void ce4(float &va, int &ia, float &pa, float &qa,
                                    float &vb, int &ib, float &pb, float &qb){
    bool sw = (va > vb) || (va == vb && ia > ib);
    if (sw){ float tv=va; va=vb; vb=tv; int ti=ia; ia=ib; ib=ti;
             float tp=pa; pa=pb; pb=tp; float tq=qa; qa=qb; qb=tq; }
}
__device__ __forceinline__ void sort8p2(float v[8], int id[8], float p[8], float q[8]){
    ce4(v[0],id[0],p[0],q[0],v[1],id[1],p[1],q[1]); ce4(v[2],id[2],p[2],q[2],v[3],id[3],p[3],q[3]);
    ce4(v[4],id[4],p[4],q[4],v[5],id[5],p[5],q[5]); ce4(v[6],id[6],p[6],q[6],v[7],id[7],p[7],q[7]);
    ce4(v[0],id[0],p[0],q[0],v[2],id[2],p[2],q[2]); ce4(v[1],id[1],p[1],q[1],v[3],id[3],p[3],q[3]);
    ce4(v[4],id[4],p[4],q[4],v[6],id[6],p[6],q[6]); ce4(v[5],id[5],p[5],q[5],v[7],id[7],p[7],q[7]);
    ce4(v[1],id[1],p[1],q[1],v[2],id[2],p[2],q[2]); ce4(v[5],id[5],p[5],q[5],v[6],id[6],p[6],q[6]);
    ce4(v[0],id[0],p[0],q[0],v[4],id[4],p[4],q[4]); ce4(v[1],id[1],p[1],q[1],v[5],id[5],p[5],q[5]);
    ce4(v[2],id[2],p[2],q[2],v[6],id[6],p[6],q[6]); ce4(v[3],id[3],p[3],q[3],v[7],id[7],p[7],q[7]);
    ce4(v[2],id[2],p[2],q[2],v[4],id[4],p[4],q[4]); ce4(v[3],id[3],p[3],q[3],v[5],id[5],p[5],q[5]);
    ce4(v[1],id[1],p[1],q[1],v[2],id[2],p[2],q[2]); ce4(v[3],id[3],p[3],q[3],v[4],id[4],p[4],q[4]);
    ce4(v[5],id[5],p[5],q[5],v[6],id[6],p[6],q[6]);
}
__device__ __forceinline__ void group_totals_g(const float v[8], const int* sameg, float gt[8]){
    int same[7];
    #pragma unroll
    for (int i=0;i<7;i++) same[i] = sameg[i];
    float gs[8];
    gs[0] = v[0];
    #pragma unroll
    for (int i=1;i<8;i++) gs[i] = v[i] + (same[i-1] ? gs[i-1] : 0.f);
    gt[7] = gs[7];
    #pragma unroll
    for (int i=6;i>=0;i--) gt[i] = same[i] ? gt[i+1] : gs[i];
}

// per-thread d[8] (7 sums + 1 max) -> block reduce -> g_part[q*PMAX+blk]
__device__ __forceinline__ void delta_reduce(float d[8], int tid, int blk){
    #pragma unroll
    for (int off=16; off; off>>=1){
        #pragma unroll
        for (int q=0;q<7;q++) d[q] += __shfl_xor_sync(0xffffffffu, d[q], off);
        d[7] = fmaxf(d[7], __shfl_xor_sync(0xffffffffu, d[7], off));
    }
    __shared__ float sw[8][8];
    int w = tid>>5;
    if ((tid&31)==0){
        #pragma unroll
        for (int q=0;q<8;q++) sw[w][q]=d[q];
    }
    __syncthreads();
    if (tid < 8){
        int q = tid;
        float a = sw[0][q];
        if (q==7){
            #pragma unroll
            for (int w2=1;w2<8;w2++) a = fmaxf(a, sw[w2][q]);
        } else {
            #pragma unroll
            for (int w2=1;w2<8;w2++) a += sw[w2][q];
        }
        g_part[q*PMAX + blk] = a;
    }
}

// tail-block: tree-reduce g_part and compute grouping scalars (256 thr)
__device__ void scalar_tail(const float* __restrict__ thres, int set, int nblk, int tid){
    int q = tid >> 5;
    int lane = tid & 31;
    float a = 0.f;
    for (int p=lane; p<nblk; p+=32){
        float xv = g_part[q*PMAX + p];
        a = (q==7) ? fmaxf(a,xv) : (a+xv);
    }
    #pragma unroll
    for (int off=16; off; off>>=1){
        float b = __shfl_xor_sync(0xffffffffu, a, off);
        a = (q==7) ? fmaxf(a,b) : (a+b);
    }
    __shared__ float sred[8];
    if (lane==0) sred[q] = a;
    __syncthreads();
    if (tid==0){
        float dmax = sred[7];
        float sigt = 1.0f/(1.0f + expf(-thres[0]));
        float sp[7], bv[7];
        int gid[8]; gid[0]=0;
        for (int i=0;i<7;i++){
            float mean = (sred[i]/dmax) * (1.0f/1048576.0f);
            float z = (mean - sigt)/0.01f;
            sp[i] = 1.0f/(1.0f + expf(-z));
            bv[i] = rintf(sp[i]);
            gid[i+1] = gid[i] + (int)bv[i];
        }
        int counts[8]; float glog[8];
        for (int g=0;g<8;g++){ counts[g]=0; glog[g]=0.f; }
        for (int rr=0;rr<8;rr++) counts[gid[rr]]++;
        for (int i=0;i<7;i++) glog[gid[i]] += logf(bv[i]==1.0f ? sp[i] : 1.0f - sp[i]);
        float gg[8];
        for (int g=0;g<8;g++) gg[g] = expf(glog[g]);
        for (int rr=0;rr<8;rr++){ g_coefs[set][rr] = gg[gid[rr]]; g_cnts[set][rr] = (float)counts[gid[rr]]; }
        for (int i=0;i<7;i++) g_sames[set][i] = (bv[i]==0.0f) ? 1 : 0;
    }
}

// ---------------- k_minmax: 512 blocks, fused last-block reduce ----------------
__global__ __launch_bounds__(256) void k_minmax(const float* __restrict__ U){
    int blk = blockIdx.x;
    int tid = threadIdx.x;
    unsigned t = (unsigned)blk*256u + tid;
    const float4* U4 = reinterpret_cast<const float4*>(U);
    float lo =  INFINITY;
    float hi = -INFINITY;
    #pragma unroll
    for (int i=0;i<16;i++){
        float4 u = U4[t + (unsigned)i*131072u];
        lo = fminf(lo, fminf(fminf(u.x,u.y), fminf(u.z,u.w)));
        hi = fmaxf(hi, fmaxf(fmaxf(u.x,u.y), fmaxf(u.z,u.w)));
    }
    #pragma unroll
    for (int off=16; off; off>>=1){
        lo = fminf(lo, __shfl_xor_sync(0xffffffffu, lo, off));
        hi = fmaxf(hi, __shfl_xor_sync(0xffffffffu, hi, off));
    }
    __shared__ float slo[8], shi[8];
    if ((tid&31)==0){ slo[tid>>5]=lo; shi[tid>>5]=hi; }
    __syncthreads();
    if (tid==0){
        #pragma unroll
        for (int w=1;w<8;w++){ lo=fminf(lo,slo[w]); hi=fmaxf(hi,shi[w]); }
        g_pmin[blk]=lo; g_pmax[blk]=hi;
    }
    __shared__ unsigned s_last;
    __threadfence();
    if (tid==0) s_last = atomicAdd(&g_cntm, 1u);
    __syncthreads();
    if (s_last == 511u){
        float l2 = fminf(g_pmin[tid], g_pmin[tid+256]);
        float h2 = fmaxf(g_pmax[tid], g_pmax[tid+256]);
        #pragma unroll
        for (int off=16; off; off>>=1){
            l2 = fminf(l2, __shfl_xor_sync(0xffffffffu, l2, off));
            h2 = fmaxf(h2, __shfl_xor_sync(0xffffffffu, h2, off));
        }
        __shared__ float sl2[8], sh2[8];
        if ((tid&31)==0){ sl2[tid>>5]=l2; sh2[tid>>5]=h2; }
        __syncthreads();
        if (tid==0){
            #pragma unroll
            for (int w=1;w<8;w++){ l2=fminf(l2,sl2[w]); h2=fmaxf(h2,sh2[w]); }
            g_min = l2; g_max = h2;
            g_cntm = 0;
        }
    }
}

// ---------------- phase 1 + concurrent split: 3072 blocks ----------------
__global__ __launch_bounds__(256) void k_phase1(const float* __restrict__ x,
                                                const float* __restrict__ U,
                                                const float* __restrict__ thres){
    int tid = threadIdx.x;
    int blk = blockIdx.x;
    if (blk >= 1024){
        int sblk = blk - 1024;
        unsigned idx = (unsigned)sblk*256u + tid;
        unsigned base = idx*16u;
        unsigned d = base & 1023u;
        unsigned n = (base >> 10) & 7u;
        unsigned b = base >> 13;
        unsigned j = (n << 20) | (b << 10) | d;
        #pragma unroll
        for (int i=0;i<4;i++){
            float4 xv = *reinterpret_cast<const float4*>(x + base + 4u*i);
            __half2 h0 = __floats2half2_rn(xv.x, xv.y);
            __half2 h1 = __floats2half2_rn(xv.z, xv.w);
            *reinterpret_cast<__half2*>(g_xh + j + 4u*i)     = h0;
            *reinterpret_cast<__half2*>(g_xh + j + 4u*i + 2) = h1;
        }
        return;
    }
    unsigned c4 = (unsigned)blk*256u + tid;
    float s0 = (g_max - g_min) / 3.0f;
    float v[4][8];
    #pragma unroll
    for (int r=0;r<8;r++){
        float4 u = reinterpret_cast<const float4*>(U)[((size_t)r<<18) + c4];
        v[0][r] = u.x - s0*floorf(u.x/s0);
        v[1][r] = u.y - s0*floorf(u.y/s0);
        v[2][r] = u.z - s0*floorf(u.z/s0);
        v[3][r] = u.w - s0*floorf(u.w/s0);
    }
    float d[8];
    #pragma unroll
    for (int q=0;q<8;q++) d[q]=0.f;
    #pragma unroll
    for (int cc=0;cc<4;cc++){
        sortv8(v[cc]);
        #pragma unroll
        for (int q=0;q<7;q++){
            float dd = v[cc][q+1]-v[cc][q];
            d[q] += dd;
            d[7] = fmaxf(d[7], dd);
        }
    }
    delta_reduce(d, tid, blk);

    __shared__ unsigned s_last;
    __threadfence();
    if (tid==0) s_last = atomicAdd(&g_cntp1, 1u);
    __syncthreads();
    if (s_last == 1023u){
        scalar_tail(thres, 0, 1024, tid);
        if (tid==0) g_cntp1 = 0;
    }
}

// ---------------- phase 2: 1 col/thread, stores nv/pay/ord, fused scalar tail ----------
__global__ __launch_bounds__(256) void k_phase2(const float* __restrict__ U, const float* __restrict__ thres){
    int tid = threadIdx.x;
    unsigned c = (unsigned)blockIdx.x*256u + tid;
    float s0 = (g_max - g_min)/3.0f;
    float s1 = s0/5.0f;

    float v[8], u[8], f0[8]; int id[8];
    #pragma unroll
    for (int r=0;r<8;r++){
        float uu = U[(size_t)r*DTOT + c];
        u[r]  = uu;
        f0[r] = floorf(uu/s0);
        v[r]  = uu - s0*f0[r];
        id[r] = r;
    }
    sort8p2(v, id, u, f0);

    float gt[8];
    group_totals_g(v, g_sames[0], gt);

    float nv[8], pay[8]; int nid[8];
    #pragma unroll
    for (int i=0;i<8;i++){
        float mean = gt[i]/g_cnts[0][i];
        float t    = g_coefs[0][i]*mean;
        float f1f  = floorf(t/s1);
        float add  = s1*f1f;
        float v0   = s0*f0[i];
        float vals1 = v0 + add;
        nv[i]  = u[i] - vals1;
        nid[i] = id[i];
        pay[i] = 85.0f*f0[i] + 17.0f*f1f;   // exact small integer
    }
    sort8p(nv, nid, pay);

    unsigned ord = 0;
    #pragma unroll
    for (int i=0;i<8;i++){
        g_nv[(size_t)i*DTOT + c]  = nv[i];
        g_pay[(size_t)i*DTOT + c] = __float2half_rn(pay[i]);
        ord |= (unsigned)nid[i] << (3*i);
    }
    g_ord[c] = ord;

    float d[8];
    d[7] = 0.f;
    #pragma unroll
    for (int q=0;q<7;q++){
        float dd = nv[q+1]-nv[q];
        d[q] = dd;
        d[7] = fmaxf(d[7], dd);
    }
    delta_reduce(d, tid, blockIdx.x);

    __shared__ unsigned s_last;
    __threadfence();
    if (tid==0) s_last = atomicAdd(&g_cntp2, 1u);
    __syncthreads();
    if (s_last == 4095u){
        scalar_tail(thres, 1, 4096, tid);
        if (tid==0) g_cntp2 = 0;
    }
}

// ---------------- final consumer: smem scatter/gather inversion ----------------
__global__ __launch_bounds__(256) void k_final2(){
    __shared__ float sqa[256*9];
    __shared__ float sqb[256*9];
    int tid = threadIdx.x;
    unsigned c2 = (unsigned)blockIdx.x*256u + tid;   // column-pair index
    float s0 = (g_max - g_min)/3.0f;
    float s1 = s0/5.0f;
    float s2 = s1/17.0f;
    float nva[8], nvb[8], paya[8], payb[8];
    #pragma unroll
    for (int i=0;i<8;i++){
        float2 nv2 = reinterpret_cast<const float2*>(g_nv)[((size_t)i<<19) + c2];
        nva[i]=nv2.x; nvb[i]=nv2.y;
        __half2 p2 = reinterpret_cast<const __half2*>(g_pay)[((size_t)i<<19) + c2];
        paya[i]=__low2float(p2); payb[i]=__high2float(p2);
    }
    uint2 ords = reinterpret_cast<const uint2*>(g_ord)[c2];

    float gta[8], gtb[8];
    group_totals_g(nva, g_sames[1], gta);
    group_totals_g(nvb, g_sames[1], gtb);
    #pragma unroll
    for (int j=0;j<8;j++){
        float ta = g_coefs[1][j]*(gta[j]/g_cnts[1][j]);
        float tb = g_coefs[1][j]*(gtb[j]/g_cnts[1][j]);
        float Qa = paya[j] + floorf(ta/s2);
        float Qb = payb[j] + floorf(tb/s2);
        sqa[tid*9 + ((ords.x>>(3*j))&7u)] = Qa;   // scatter to orig-row slot
        sqb[tid*9 + ((ords.y>>(3*j))&7u)] = Qb;
    }
    #pragma unroll
    for (int r=0;r<8;r++){
        __half2 h = __floats2half2_rn(sqa[tid*9 + r], sqb[tid*9 + r]);
        reinterpret_cast<__half2*>(g_wh)[((size_t)r<<19) + c2] = h;
    }
}

// ---------------- fp16 mma.sync GEMM: K=64 stages, 3-stage cp.async, x4-trans B ----------
#define SA_STRIDE 72          // 64 + 8 pad halfs
#define SB_STRIDE 136         // 128 + 8 pad halfs
#define SA_STAGE  (128*SA_STRIDE)
#define SB_STAGE  (64*SB_STRIDE)
#define NSTG 3
#define NIT 16                // 1024 / 64
#define SMEM_HALFS (NSTG*SA_STAGE + NSTG*SB_STAGE)
#define SMEM_BYTES (SMEM_HALFS*2)

__device__ __forceinline__ void ldsm_x4(uint32_t r[4], uint32_t addr){
    asm volatile("ldmatrix.sync.aligned.m8n8.x4.shared.b16 {%0,%1,%2,%3}, [%4];"
        : "=r"(r[0]),"=r"(r[1]),"=r"(r[2]),"=r"(r[3]) : "r"(addr));
}
__device__ __forceinline__ void ldsm_x4t(uint32_t r[4], uint32_t addr){
    asm volatile("ldmatrix.sync.aligned.m8n8.x4.trans.shared.b16 {%0,%1,%2,%3}, [%4];"
        : "=r"(r[0]),"=r"(r[1]),"=r"(r[2]),"=r"(r[3]) : "r"(addr));
}
__device__ __forceinline__ void mma16816(float c[4], const uint32_t a[4], const uint32_t b0, const uint32_t b1){
    asm volatile("mma.sync.aligned.m16n8k16.row.col.f32.f16.f16.f32 "
        "{%0,%1,%2,%3}, {%4,%5,%6,%7}, {%8,%9}, {%0,%1,%2,%3};"
        : "+f"(c[0]),"+f"(c[1]),"+f"(c[2]),"+f"(c[3])
        : "r"(a[0]),"r"(a[1]),"r"(a[2]),"r"(a[3]), "r"(b0),"r"(b1));
}
__device__ __forceinline__ void cpasync16(uint32_t dst, const void* src){
    asm volatile("cp.async.cg.shared.global [%0], [%1], 16;" :: "r"(dst), "l"(src));
}

// one K=64 stage: A 128x64 halfs (4 chunks/thread), B 64x128 halfs (4 chunks/thread)
__device__ __forceinline__ void gemm_load_stage(
    const __half* Ah, const __half* Bn,
    uint32_t sA_u, uint32_t sB_u,
    int bm, int bn, int k0, int st, int tid)
{
    #pragma unroll
    for (int i=0;i<4;i++){
        int q = tid + i*256;
        int r  = q >> 3, sg = q & 7;      // 128 rows x 8 segs (8 halfs)
        const __half* srch = Ah + (size_t)(bm+r)*1024 + k0 + sg*8;
        uint32_t off = (uint32_t)(st*SA_STAGE + r*SA_STRIDE + sg*8)*2u;
        cpasync16(sA_u + off, srch);
        int kr = q >> 4, ns = q & 15;     // 64 k-rows x 16 segs (8 halfs)
        const __half* srcb = Bn + (size_t)(k0+kr)*1024 + bn + ns*8;
        uint32_t offb = (uint32_t)(st*SB_STAGE + kr*SB_STRIDE + ns*8)*2u;
        cpasync16(sB_u + offb, srcb);
    }
    asm volatile("cp.async.commit_group;");
}

__global__ __launch_bounds__(256) void k_gemm_h(float* __restrict__ out){
    extern __shared__ __half smem[];
    __half* sA = smem;
    __half* sB = smem + NSTG*SA_STAGE;

    int n  = blockIdx.z;
    int bm = blockIdx.y * 128;
    int bn = blockIdx.x * 128;
    const __half* An = g_xh + ((size_t)n << 20);
    const __half* Bn = g_wh + ((size_t)n << 20);

    int tid  = threadIdx.x;
    int lane = tid & 31;
    int warp = tid >> 5;
    int wm = (warp >> 1) * 32;
    int wn = (warp & 1) * 64;

    uint32_t sA_u = (uint32_t)__cvta_generic_to_shared(sA);
    uint32_t sB_u = (uint32_t)__cvta_generic_to_shared(sB);

    float c[2][8][4];
    #pragma unroll
    for (int mt=0;mt<2;mt++)
        #pragma unroll
        for (int nt=0;nt<8;nt++)
            #pragma unroll
            for (int q=0;q<4;q++) c[mt][nt][q] = 0.f;

    gemm_load_stage(An, Bn, sA_u, sB_u, bm, bn, 0,  0, tid);
    gemm_load_stage(An, Bn, sA_u, sB_u, bm, bn, 64, 1, tid);

    for (int it=0; it<NIT; it++){
        int st = it % 3;
        if (it < NIT-1) asm volatile("cp.async.wait_group 1;");
        else            asm volatile("cp.async.wait_group 0;");
        __syncthreads();
        if (it + 2 < NIT)
            gemm_load_stage(An, Bn, sA_u, sB_u, bm, bn, (it+2)*64, (it+2)%3, tid);

        #pragma unroll
        for (int kk=0; kk<64; kk+=16){
            uint32_t ah[2][4], bf[4][4];
            #pragma unroll
            for (int mt=0; mt<2; mt++){
                int row = wm + mt*16 + (lane & 15);
                int col = kk + ((lane >> 4) << 3);
                uint32_t off = (uint32_t)(st*SA_STAGE + row*SA_STRIDE + col)*2u;
                ldsm_x4(ah[mt], sA_u + off);
            }
            #pragma unroll
            for (int nt2=0; nt2<4; nt2++){
                int krow = kk + (lane & 15);
                int coln = wn + (nt2*2 + (lane >> 4))*8;
                uint32_t off = (uint32_t)(st*SB_STAGE + krow*SB_STRIDE + coln)*2u;
                ldsm_x4t(bf[nt2], sB_u + off);
            }
            #pragma unroll
            for (int mt=0;mt<2;mt++)
                #pragma unroll
                for (int nt2=0;nt2<4;nt2++){
                    mma16816(c[mt][nt2*2+0], ah[mt], bf[nt2][0], bf[nt2][1]);
                    mma16816(c[mt][nt2*2+1], ah[mt], bf[nt2][2], bf[nt2][3]);
                }
        }
    }

    float s2 = ((g_max - g_min)/3.0f/5.0f)/17.0f;
    #pragma unroll
    for (int mt=0;mt<2;mt++){
        int r0 = bm + wm + mt*16 + (lane >> 2);
        #pragma unroll
        for (int nt=0;nt<8;nt++){
            int cb = bn + wn + nt*8 + (lane & 3)*2;
            float2 v0 = make_float2(c[mt][nt][0]*s2, c[mt][nt][1]*s2);
            float2 v1 = make_float2(c[mt][nt][2]*s2, c[mt][nt][3]*s2);
            *reinterpret_cast<float2*>(out + (size_t)r0*8192 + n*1024 + cb)       = v0;
            *reinterpret_cast<float2*>(out + (size_t)(r0+8)*8192 + n*1024 + cb)   = v1;
        }
    }
}

// ---------------- launch ----------------
extern "C" void kernel_launch(void* const* d_in, const int* in_sizes, int n_in,
                              void* d_out, int out_size) {
    const float* x     = (const float*)d_in[0];   // [1024, 8, 1024]
    const float* U     = (const float*)d_in[1];   // [8, 1048576]
    const float* thres = (const float*)d_in[2];   // [1]
    float* out = (float*)d_out;                   // [1024, 8, 1024]

    cudaFuncSetAttribute(k_gemm_h, cudaFuncAttributeMaxDynamicSharedMemorySize, SMEM_BYTES);

    k_minmax<<<512,256>>>(U);                   // U min/max, fused tail reduce
    k_phase1<<<3072,256>>>(x, U, thres);        // pass1 FIRST (blocks 0..1023) + split behind
    k_phase2<<<4096,256>>>(U, thres);           // pass2 + stores + fused scalar tail (set 1)
    k_final2<<<2048,256>>>();                   // light consumer: smem-inverted Q, coalesced
    k_gemm_h<<<dim3(8, 8, 8), 256, SMEM_BYTES>>>(out);
}